// round 2
// baseline (speedup 1.0000x reference)
#include <cuda_runtime.h>
#include <math.h>
#include <stdint.h>

#define B 512
#define S 400
#define V 50000
#define E 512
#define H 256
#define EMB 128
#define KX (E + EMB + H)   /* 896: [context | embed | h0] */
#define G4 (4*H)           /* 1024 */

#define OUT_OUTPUT ((size_t)0)
#define OUT_COV    ((size_t)B*V)
#define OUT_HT     (OUT_COV  + (size_t)B*S)
#define OUT_CT     (OUT_HT   + (size_t)B*H)
#define OUT_ATTN   (OUT_CT   + (size_t)B*H)
#define OUT_LOSS   (OUT_ATTN + (size_t)B*S)

// ---------------- scratch (static device memory; no allocation) ----------------
__device__ float g_context[B*E];
__device__ float g_embed[B*EMB];
__device__ float g_xcat[B*KX];
__device__ float g_Wcat[G4*KX];
__device__ float g_bcat[G4];
__device__ float g_gates[B*G4];
__device__ float g_cw[B];
__device__ float g_exw[B];
__device__ float g_pgen[B];
__device__ float g_whapp[(size_t)B*S*H];   // 209.7 MB
__device__ float g_wsapp[B*H];
__device__ float g_energy[B*S];
__device__ float g_rowmax[B];
__device__ float g_rowinv[B];
__device__ float g_covpart[B];

// ---------------- helpers ----------------
__device__ __forceinline__ float sigmoidf_(float x) { return 1.f / (1.f + expf(-x)); }

__device__ __forceinline__ float blk_sum(float v, float* red) {
    int tid = threadIdx.x;
    #pragma unroll
    for (int o = 16; o; o >>= 1) v += __shfl_down_sync(0xffffffffu, v, o);
    if ((tid & 31) == 0) red[tid >> 5] = v;
    __syncthreads();
    float r;
    if (tid < 32) {
        int nw = (blockDim.x + 31) >> 5;
        r = (tid < nw) ? red[tid] : 0.f;
        #pragma unroll
        for (int o = 16; o; o >>= 1) r += __shfl_down_sync(0xffffffffu, r, o);
        if (tid == 0) red[0] = r;
    }
    __syncthreads();
    r = red[0];
    __syncthreads();
    return r;
}

__device__ __forceinline__ float blk_max(float v, float* red) {
    int tid = threadIdx.x;
    #pragma unroll
    for (int o = 16; o; o >>= 1) v = fmaxf(v, __shfl_down_sync(0xffffffffu, v, o));
    if ((tid & 31) == 0) red[tid >> 5] = v;
    __syncthreads();
    float r;
    if (tid < 32) {
        int nw = (blockDim.x + 31) >> 5;
        r = (tid < nw) ? red[tid] : -1e30f;
        #pragma unroll
        for (int o = 16; o; o >>= 1) r = fmaxf(r, __shfl_down_sync(0xffffffffu, r, o));
        if (tid == 0) red[0] = r;
    }
    __syncthreads();
    r = red[0];
    __syncthreads();
    return r;
}

// ---------------- K1: context = attn @ enc_out, embed gather, p_gen partials ----------------
__global__ void k_context(const float* __restrict__ attn, const float* __restrict__ enc_out,
                          const int* __restrict__ dec_input, const float* __restrict__ emb_table,
                          const float* __restrict__ wh, const float* __restrict__ wx) {
    int b = blockIdx.x, tid = threadIdx.x;  // 256 threads
    __shared__ float sa[S];
    __shared__ float red[32];
    for (int s = tid; s < S; s += 256) sa[s] = attn[(size_t)b*S + s];
    __syncthreads();
    const float* eb = enc_out + (size_t)b*S*E;
    float a0 = 0.f, a1 = 0.f;
    #pragma unroll 4
    for (int s = 0; s < S; s++) {
        float a = sa[s];
        a0 += a * eb[(size_t)s*E + tid];
        a1 += a * eb[(size_t)s*E + 256 + tid];
    }
    g_context[b*E + tid]       = a0;
    g_context[b*E + 256 + tid] = a1;
    float cw = blk_sum(a0*wh[tid] + a1*wh[256+tid], red);
    if (tid == 0) g_cw[b] = cw;
    float ew = 0.f;
    if (tid < EMB) {
        float e = emb_table[(size_t)dec_input[b]*EMB + tid];
        g_embed[b*EMB + tid] = e;
        ew = e * wx[tid];
    }
    float exw = blk_sum(ew, red);
    if (tid == 0) g_exw[b] = exw;
}

// ---------------- pack weights / inputs for the fused gates GEMM ----------------
__global__ void k_packw(const float* __restrict__ W_ih, const float* __restrict__ W_hh,
                        const float* __restrict__ b_ih, const float* __restrict__ b_hh) {
    int idx = blockIdx.x*blockDim.x + threadIdx.x;
    if (idx < G4*KX) {
        int n = idx / KX, k = idx % KX;
        g_Wcat[idx] = (k < E+EMB) ? W_ih[(size_t)n*(E+EMB) + k] : W_hh[(size_t)n*H + (k - (E+EMB))];
    }
    if (idx < G4) g_bcat[idx] = b_ih[idx] + b_hh[idx];
}

__global__ void k_packx(const float* __restrict__ h0) {
    int idx = blockIdx.x*blockDim.x + threadIdx.x;
    if (idx < B*KX) {
        int b = idx / KX, k = idx % KX;
        float v;
        if (k < E)            v = g_context[b*E + k];
        else if (k < E+EMB)   v = g_embed[b*EMB + (k - E)];
        else                  v = h0[b*H + (k - E - EMB)];
        g_xcat[idx] = v;
    }
}

// ---------------- generic SGEMM: C[m,n] = bias[n] + sum_k A[m,k] * W[n,k] ----------------
// BM=BN=128, BK=8, 256 threads, 8x8 microtile. M must be a multiple of 128 (true for all calls).
__global__ void sgemm_bt(const float* __restrict__ A, const float* __restrict__ W,
                         const float* __restrict__ bias, float* __restrict__ C,
                         int M, int N, int K) {
    __shared__ float As[8][128];
    __shared__ float Bs[8][128];
    const int tid = threadIdx.x;
    const int bm = blockIdx.y * 128;
    const int bn = blockIdx.x * 128;
    const int tr = (tid / 16) * 8;
    const int tc = (tid % 16) * 8;
    const int lr = tid >> 1;
    const int lk = (tid & 1) * 4;

    float acc[8][8];
    #pragma unroll
    for (int i = 0; i < 8; i++)
        #pragma unroll
        for (int j = 0; j < 8; j++) acc[i][j] = 0.f;

    for (int k0 = 0; k0 < K; k0 += 8) {
        float4 a4 = *reinterpret_cast<const float4*>(&A[(size_t)(bm + lr)*K + k0 + lk]);
        float4 w4 = make_float4(0.f, 0.f, 0.f, 0.f);
        if (bn + lr < N)
            w4 = *reinterpret_cast<const float4*>(&W[(size_t)(bn + lr)*K + k0 + lk]);
        As[lk+0][lr] = a4.x; As[lk+1][lr] = a4.y; As[lk+2][lr] = a4.z; As[lk+3][lr] = a4.w;
        Bs[lk+0][lr] = w4.x; Bs[lk+1][lr] = w4.y; Bs[lk+2][lr] = w4.z; Bs[lk+3][lr] = w4.w;
        __syncthreads();
        #pragma unroll
        for (int kk = 0; kk < 8; kk++) {
            float a[8], bb[8];
            #pragma unroll
            for (int i = 0; i < 8; i++) a[i] = As[kk][tr + i];
            #pragma unroll
            for (int j = 0; j < 8; j++) bb[j] = Bs[kk][tc + j];
            #pragma unroll
            for (int i = 0; i < 8; i++)
                #pragma unroll
                for (int j = 0; j < 8; j++) acc[i][j] += a[i] * bb[j];
        }
        __syncthreads();
    }
    #pragma unroll
    for (int i = 0; i < 8; i++) {
        size_t m = (size_t)(bm + tr + i);
        #pragma unroll
        for (int j = 0; j < 8; j++) {
            int n = bn + tc + j;
            if (n < N) C[m*N + n] = acc[i][j] + bias[n];
        }
    }
}

// ---------------- LSTM cell + p_gen ----------------
__global__ void k_lstm(const float* __restrict__ c0, const float* __restrict__ ws,
                       float* __restrict__ out) {
    int b = blockIdx.x, h = threadIdx.x;  // 256 threads
    __shared__ float red[32];
    const float* g = g_gates + (size_t)b*G4;
    float ig = sigmoidf_(g[h]);
    float fg = sigmoidf_(g[H + h]);
    float gg = tanhf(g[2*H + h]);
    float og = sigmoidf_(g[3*H + h]);
    float c  = fg * c0[b*H + h] + ig * gg;
    float ht = og * tanhf(c);
    out[OUT_CT + (size_t)b*H + h] = c;
    out[OUT_HT + (size_t)b*H + h] = ht;
    float hw = blk_sum(ht * ws[h], red);
    if (h == 0) g_pgen[b] = sigmoidf_(g_cw[b] + hw + g_exw[b]);
}

// ---------------- vocab softmax stats (online max/sum over V) ----------------
__global__ void k_rowstats(const float* __restrict__ out) {
    int b = blockIdx.x, tid = threadIdx.x;  // 1024 threads
    const float* row = out + (size_t)b*V;
    float m = -1e30f, s = 0.f;
    for (int v = tid; v < V; v += 1024) {
        float x = row[v];
        if (x > m) { s = s*expf(m - x) + 1.f; m = x; }
        else       { s += expf(x - m); }
    }
    __shared__ float sm[1024], ss[1024];
    sm[tid] = m; ss[tid] = s;
    __syncthreads();
    for (int off = 512; off; off >>= 1) {
        if (tid < off) {
            float m2 = sm[tid+off], s2 = ss[tid+off];
            float M = fmaxf(sm[tid], m2);
            ss[tid] = ss[tid]*expf(sm[tid] - M) + s2*expf(m2 - M);
            sm[tid] = M;
        }
        __syncthreads();
    }
    if (tid == 0) { g_rowmax[b] = sm[0]; g_rowinv[b] = 1.f/ss[0]; }
}

// ---------------- out = p_gen * softmax(logits) (in place over d_out) ----------------
__global__ void k_norm(float* __restrict__ out) {
    size_t idx = (size_t)blockIdx.x*blockDim.x + threadIdx.x;
    if (idx < (size_t)B*V) {
        int b = (int)(idx / V);
        out[idx] = g_pgen[b] * expf(out[idx] - g_rowmax[b]) * g_rowinv[b];
    }
}

// ---------------- energy[b,s] = tanh(whapp + wsapp + cov*awc) . av ----------------
__global__ void k_energy(const float* __restrict__ coverage, const float* __restrict__ awc,
                         const float* __restrict__ av) {
    int b = blockIdx.y;
    int warp = threadIdx.x >> 5, lane = threadIdx.x & 31;
    int s = blockIdx.x*8 + warp;
    __shared__ float sws[H], sawc[H], sav[H];
    if (threadIdx.x < H) {
        sws[threadIdx.x]  = g_wsapp[b*H + threadIdx.x];
        sawc[threadIdx.x] = awc[threadIdx.x];
        sav[threadIdx.x]  = av[threadIdx.x];
    }
    __syncthreads();
    float cov = coverage[(size_t)b*S + s];
    const float* wa = g_whapp + ((size_t)b*S + s)*H;
    float acc = 0.f;
    #pragma unroll
    for (int h = lane; h < H; h += 32)
        acc += tanhf(wa[h] + sws[h] + cov*sawc[h]) * sav[h];
    #pragma unroll
    for (int o = 16; o; o >>= 1) acc += __shfl_down_sync(0xffffffffu, acc, o);
    if (lane == 0) g_energy[b*S + s] = acc;
}

// ---------------- attention softmax over S + coverage outputs + loss partials ----------------
__global__ void k_attn(const float* __restrict__ coverage, float* __restrict__ out) {
    int b = blockIdx.x, tid = threadIdx.x;  // 512 threads
    __shared__ float red[32];
    float e = (tid < S) ? g_energy[b*S + tid] : -1e30f;
    float m = blk_max(e, red);
    float ex = (tid < S) ? expf(e - m) : 0.f;
    float sum = blk_sum(ex, red);
    float part = 0.f;
    if (tid < S) {
        float a = ex / sum;
        out[OUT_ATTN + (size_t)b*S + tid] = a;
        float c = coverage[(size_t)b*S + tid];
        out[OUT_COV + (size_t)b*S + tid] = c + a;
        part = fminf(a, c);
    }
    float ps = blk_sum(part, red);
    if (tid == 0) g_covpart[b] = ps;
}

__global__ void k_loss(float* __restrict__ out) {
    __shared__ float red[32];
    float v = g_covpart[threadIdx.x];  // 512 threads == B
    float s = blk_sum(v, red);
    if (threadIdx.x == 0) out[OUT_LOSS] = s;
}

// ---------------- scatter: last-s-wins set semantics, added onto p_gen*p_vocab ----------------
__global__ void k_scatter(const int* __restrict__ enc_inputs, float* __restrict__ out) {
    int b = blockIdx.x, tid = threadIdx.x;  // 512 threads
    __shared__ int   sidx[S];
    __shared__ float sat[S];
    if (tid < S) {
        sidx[tid] = enc_inputs[(size_t)b*S + tid];
        sat[tid]  = out[OUT_ATTN + (size_t)b*S + tid];
    }
    __syncthreads();
    if (tid < S) {
        int v = sidx[tid];
        bool win = true;
        for (int s2 = tid + 1; s2 < S; s2++)
            if (sidx[s2] == v) { win = false; break; }
        if (win) {
            float g = g_pgen[b];
            size_t o = (size_t)b*V + v;
            out[o] += (1.f - g) * sat[tid];   // unique winner per (b,v): race-free RMW
        }
    }
}

// ---------------- host launcher ----------------
extern "C" void kernel_launch(void* const* d_in, const int* in_sizes, int n_in,
                              void* d_out, int out_size) {
    const float* coverage   = (const float*)d_in[0];
    const float* enc_out    = (const float*)d_in[1];
    const float* h0         = (const float*)d_in[2];
    const float* c0         = (const float*)d_in[3];
    const float* attn       = (const float*)d_in[4];
    const int*   dec_input  = (const int*)d_in[5];
    const int*   enc_inputs = (const int*)d_in[6];
    const float* emb_table  = (const float*)d_in[7];
    const float* W_ih       = (const float*)d_in[8];
    const float* W_hh       = (const float*)d_in[9];
    const float* b_ih       = (const float*)d_in[10];
    const float* b_hh       = (const float*)d_in[11];
    const float* awh_W      = (const float*)d_in[12];
    const float* awh_b      = (const float*)d_in[13];
    const float* aws_W      = (const float*)d_in[14];
    const float* aws_b      = (const float*)d_in[15];
    const float* awc        = (const float*)d_in[16];
    const float* av         = (const float*)d_in[17];
    const float* wh         = (const float*)d_in[18];
    const float* ws         = (const float*)d_in[19];
    const float* wx         = (const float*)d_in[20];
    const float* v_W        = (const float*)d_in[21];
    const float* v_b        = (const float*)d_in[22];
    float* out = (float*)d_out;

    float *p_xcat, *p_Wcat, *p_bcat, *p_gates, *p_whapp, *p_wsapp;
    cudaGetSymbolAddress((void**)&p_xcat,  g_xcat);
    cudaGetSymbolAddress((void**)&p_Wcat,  g_Wcat);
    cudaGetSymbolAddress((void**)&p_bcat,  g_bcat);
    cudaGetSymbolAddress((void**)&p_gates, g_gates);
    cudaGetSymbolAddress((void**)&p_whapp, g_whapp);
    cudaGetSymbolAddress((void**)&p_wsapp, g_wsapp);

    // context / embed / p_gen partials
    k_context<<<B, 256>>>(attn, enc_out, dec_input, emb_table, wh, wx);
    // pack for gates GEMM
    k_packw<<<(G4*KX + 255)/256, 256>>>(W_ih, W_hh, b_ih, b_hh);
    k_packx<<<(B*KX + 255)/256, 256>>>(h0);
    // gates = [context|embed|h0] @ [W_ih|W_hh]^T + (b_ih+b_hh)
    sgemm_bt<<<dim3(G4/128, B/128), 256>>>(p_xcat, p_Wcat, p_bcat, p_gates, B, G4, KX);
    // LSTM -> h_t, c_t (into d_out), p_gen
    k_lstm<<<B, 256>>>(c0, ws, out);
    // wh_app = enc_out @ awh_W^T + awh_b   (the big 53.7 GF GEMM)
    sgemm_bt<<<dim3(H/128, (B*S)/128), 256>>>(enc_out, awh_W, awh_b, p_whapp, B*S, H, E);
    // ws_app = h_t @ aws_W^T + aws_b
    sgemm_bt<<<dim3(H/128, B/128), 256>>>(out + OUT_HT, aws_W, aws_b, p_wsapp, B, H, H);
    // logits = h_t @ v_W^T + v_b  -> staged into d_out[0 : B*V]
    sgemm_bt<<<dim3((V + 127)/128, B/128), 256>>>(out + OUT_HT, v_W, v_b, out, B, V, H);
    // vocab softmax
    k_rowstats<<<B, 1024>>>(out);
    k_norm<<<(int)(((size_t)B*V + 255)/256), 256>>>(out);
    // attention energy -> softmax -> coverage outputs
    k_energy<<<dim3(S/8, B), 256>>>(coverage, awc, av);
    k_attn<<<B, 512>>>(coverage, out);
    k_loss<<<1, 512>>>(out);
    // pointer-generator scatter (after k_norm)
    k_scatter<<<B, 512>>>(enc_inputs, out);
}

// round 3
// speedup vs baseline: 1.0004x; 1.0004x over previous
#include <cuda_runtime.h>
#include <math.h>
#include <stdint.h>

#define B 512
#define S 400
#define V 50000
#define E 512
#define H 256
#define EMB 128
#define KX (E + EMB + H)   /* 896: [context | embed | h0] */
#define G4 (4*H)           /* 1024 */

#define OUT_OUTPUT ((size_t)0)
#define OUT_COV    ((size_t)B*V)
#define OUT_HT     (OUT_COV  + (size_t)B*S)
#define OUT_CT     (OUT_HT   + (size_t)B*H)
#define OUT_ATTN   (OUT_CT   + (size_t)B*H)
#define OUT_LOSS   (OUT_ATTN + (size_t)B*S)

// ---------------- scratch (static device memory; no allocation) ----------------
__device__ float g_context[B*E];
__device__ float g_embed[B*EMB];
__device__ float g_xcat[B*KX];
__device__ float g_Wcat[G4*KX];
__device__ float g_bcat[G4];
__device__ float g_gates[B*G4];
__device__ float g_cw[B];
__device__ float g_exw[B];
__device__ float g_pgen[B];
__device__ float g_whapp[(size_t)B*S*H];   // 209.7 MB
__device__ float g_wsapp[B*H];
__device__ float g_energy[B*S];
__device__ float g_rowmax[B];
__device__ float g_rowinv[B];
__device__ float g_covpart[B];

// ---------------- helpers ----------------
__device__ __forceinline__ float sigmoidf_(float x) { return 1.f / (1.f + expf(-x)); }

__device__ __forceinline__ float blk_sum(float v, float* red) {
    int tid = threadIdx.x;
    #pragma unroll
    for (int o = 16; o; o >>= 1) v += __shfl_down_sync(0xffffffffu, v, o);
    if ((tid & 31) == 0) red[tid >> 5] = v;
    __syncthreads();
    float r;
    if (tid < 32) {
        int nw = (blockDim.x + 31) >> 5;
        r = (tid < nw) ? red[tid] : 0.f;
        #pragma unroll
        for (int o = 16; o; o >>= 1) r += __shfl_down_sync(0xffffffffu, r, o);
        if (tid == 0) red[0] = r;
    }
    __syncthreads();
    r = red[0];
    __syncthreads();
    return r;
}

__device__ __forceinline__ float blk_max(float v, float* red) {
    int tid = threadIdx.x;
    #pragma unroll
    for (int o = 16; o; o >>= 1) v = fmaxf(v, __shfl_down_sync(0xffffffffu, v, o));
    if ((tid & 31) == 0) red[tid >> 5] = v;
    __syncthreads();
    float r;
    if (tid < 32) {
        int nw = (blockDim.x + 31) >> 5;
        r = (tid < nw) ? red[tid] : -1e30f;
        #pragma unroll
        for (int o = 16; o; o >>= 1) r = fmaxf(r, __shfl_down_sync(0xffffffffu, r, o));
        if (tid == 0) red[0] = r;
    }
    __syncthreads();
    r = red[0];
    __syncthreads();
    return r;
}

// ---------------- K1: context = attn @ enc_out, embed gather, p_gen partials ----------------
__global__ void k_context(const float* __restrict__ attn, const float* __restrict__ enc_out,
                          const int* __restrict__ dec_input, const float* __restrict__ emb_table,
                          const float* __restrict__ wh, const float* __restrict__ wx) {
    int b = blockIdx.x, tid = threadIdx.x;  // 256 threads
    __shared__ float sa[S];
    __shared__ float red[32];
    for (int s = tid; s < S; s += 256) sa[s] = attn[(size_t)b*S + s];
    __syncthreads();
    const float* eb = enc_out + (size_t)b*S*E;
    float a0 = 0.f, a1 = 0.f;
    #pragma unroll 4
    for (int s = 0; s < S; s++) {
        float a = sa[s];
        a0 += a * eb[(size_t)s*E + tid];
        a1 += a * eb[(size_t)s*E + 256 + tid];
    }
    g_context[b*E + tid]       = a0;
    g_context[b*E + 256 + tid] = a1;
    float cw = blk_sum(a0*wh[tid] + a1*wh[256+tid], red);
    if (tid == 0) g_cw[b] = cw;
    float ew = 0.f;
    if (tid < EMB) {
        float e = emb_table[(size_t)dec_input[b]*EMB + tid];
        g_embed[b*EMB + tid] = e;
        ew = e * wx[tid];
    }
    float exw = blk_sum(ew, red);
    if (tid == 0) g_exw[b] = exw;
}

// ---------------- pack weights / inputs for the fused gates GEMM ----------------
__global__ void k_packw(const float* __restrict__ W_ih, const float* __restrict__ W_hh,
                        const float* __restrict__ b_ih, const float* __restrict__ b_hh) {
    int idx = blockIdx.x*blockDim.x + threadIdx.x;
    if (idx < G4*KX) {
        int n = idx / KX, k = idx % KX;
        g_Wcat[idx] = (k < E+EMB) ? W_ih[(size_t)n*(E+EMB) + k] : W_hh[(size_t)n*H + (k - (E+EMB))];
    }
    if (idx < G4) g_bcat[idx] = b_ih[idx] + b_hh[idx];
}

__global__ void k_packx(const float* __restrict__ h0) {
    int idx = blockIdx.x*blockDim.x + threadIdx.x;
    if (idx < B*KX) {
        int b = idx / KX, k = idx % KX;
        float v;
        if (k < E)            v = g_context[b*E + k];
        else if (k < E+EMB)   v = g_embed[b*EMB + (k - E)];
        else                  v = h0[b*H + (k - E - EMB)];
        g_xcat[idx] = v;
    }
}

// ---------------- generic SGEMM: C[m,n] = bias[n] + sum_k A[m,k] * W[n,k] ----------------
// BM=BN=128, BK=8, 256 threads, 8x8 microtile. M must be a multiple of 128 (true for all calls).
__global__ void sgemm_bt(const float* __restrict__ A, const float* __restrict__ W,
                         const float* __restrict__ bias, float* __restrict__ C,
                         int M, int N, int K) {
    __shared__ float As[8][128];
    __shared__ float Bs[8][128];
    const int tid = threadIdx.x;
    const int bm = blockIdx.y * 128;
    const int bn = blockIdx.x * 128;
    const int tr = (tid / 16) * 8;
    const int tc = (tid % 16) * 8;
    const int lr = tid >> 1;
    const int lk = (tid & 1) * 4;

    float acc[8][8];
    #pragma unroll
    for (int i = 0; i < 8; i++)
        #pragma unroll
        for (int j = 0; j < 8; j++) acc[i][j] = 0.f;

    for (int k0 = 0; k0 < K; k0 += 8) {
        float4 a4 = *reinterpret_cast<const float4*>(&A[(size_t)(bm + lr)*K + k0 + lk]);
        float4 w4 = make_float4(0.f, 0.f, 0.f, 0.f);
        if (bn + lr < N)
            w4 = *reinterpret_cast<const float4*>(&W[(size_t)(bn + lr)*K + k0 + lk]);
        As[lk+0][lr] = a4.x; As[lk+1][lr] = a4.y; As[lk+2][lr] = a4.z; As[lk+3][lr] = a4.w;
        Bs[lk+0][lr] = w4.x; Bs[lk+1][lr] = w4.y; Bs[lk+2][lr] = w4.z; Bs[lk+3][lr] = w4.w;
        __syncthreads();
        #pragma unroll
        for (int kk = 0; kk < 8; kk++) {
            float a[8], bb[8];
            #pragma unroll
            for (int i = 0; i < 8; i++) a[i] = As[kk][tr + i];
            #pragma unroll
            for (int j = 0; j < 8; j++) bb[j] = Bs[kk][tc + j];
            #pragma unroll
            for (int i = 0; i < 8; i++)
                #pragma unroll
                for (int j = 0; j < 8; j++) acc[i][j] += a[i] * bb[j];
        }
        __syncthreads();
    }
    #pragma unroll
    for (int i = 0; i < 8; i++) {
        size_t m = (size_t)(bm + tr + i);
        #pragma unroll
        for (int j = 0; j < 8; j++) {
            int n = bn + tc + j;
            if (n < N) C[m*N + n] = acc[i][j] + bias[n];
        }
    }
}

// ---------------- LSTM cell + p_gen ----------------
__global__ void k_lstm(const float* __restrict__ c0, const float* __restrict__ ws,
                       float* __restrict__ out) {
    int b = blockIdx.x, h = threadIdx.x;  // 256 threads
    __shared__ float red[32];
    const float* g = g_gates + (size_t)b*G4;
    float ig = sigmoidf_(g[h]);
    float fg = sigmoidf_(g[H + h]);
    float gg = tanhf(g[2*H + h]);
    float og = sigmoidf_(g[3*H + h]);
    float c  = fg * c0[b*H + h] + ig * gg;
    float ht = og * tanhf(c);
    out[OUT_CT + (size_t)b*H + h] = c;
    out[OUT_HT + (size_t)b*H + h] = ht;
    float hw = blk_sum(ht * ws[h], red);
    if (h == 0) g_pgen[b] = sigmoidf_(g_cw[b] + hw + g_exw[b]);
}

// ---------------- vocab softmax stats (online max/sum over V) ----------------
__global__ void k_rowstats(const float* __restrict__ out) {
    int b = blockIdx.x, tid = threadIdx.x;  // 1024 threads
    const float* row = out + (size_t)b*V;
    float m = -1e30f, s = 0.f;
    for (int v = tid; v < V; v += 1024) {
        float x = row[v];
        if (x > m) { s = s*expf(m - x) + 1.f; m = x; }
        else       { s += expf(x - m); }
    }
    __shared__ float sm[1024], ss[1024];
    sm[tid] = m; ss[tid] = s;
    __syncthreads();
    for (int off = 512; off; off >>= 1) {
        if (tid < off) {
            float m2 = sm[tid+off], s2 = ss[tid+off];
            float M = fmaxf(sm[tid], m2);
            ss[tid] = ss[tid]*expf(sm[tid] - M) + s2*expf(m2 - M);
            sm[tid] = M;
        }
        __syncthreads();
    }
    if (tid == 0) { g_rowmax[b] = sm[0]; g_rowinv[b] = 1.f/ss[0]; }
}

// ---------------- out = p_gen * softmax(logits) (in place over d_out) ----------------
__global__ void k_norm(float* __restrict__ out) {
    size_t idx = (size_t)blockIdx.x*blockDim.x + threadIdx.x;
    if (idx < (size_t)B*V) {
        int b = (int)(idx / V);
        out[idx] = g_pgen[b] * expf(out[idx] - g_rowmax[b]) * g_rowinv[b];
    }
}

// ---------------- energy[b,s] = tanh(whapp + wsapp + cov*awc) . av ----------------
__global__ void k_energy(const float* __restrict__ coverage, const float* __restrict__ awc,
                         const float* __restrict__ av) {
    int b = blockIdx.y;
    int warp = threadIdx.x >> 5, lane = threadIdx.x & 31;
    int s = blockIdx.x*8 + warp;
    __shared__ float sws[H], sawc[H], sav[H];
    if (threadIdx.x < H) {
        sws[threadIdx.x]  = g_wsapp[b*H + threadIdx.x];
        sawc[threadIdx.x] = awc[threadIdx.x];
        sav[threadIdx.x]  = av[threadIdx.x];
    }
    __syncthreads();
    float cov = coverage[(size_t)b*S + s];
    const float* wa = g_whapp + ((size_t)b*S + s)*H;
    float acc = 0.f;
    #pragma unroll
    for (int h = lane; h < H; h += 32)
        acc += tanhf(wa[h] + sws[h] + cov*sawc[h]) * sav[h];
    #pragma unroll
    for (int o = 16; o; o >>= 1) acc += __shfl_down_sync(0xffffffffu, acc, o);
    if (lane == 0) g_energy[b*S + s] = acc;
}

// ---------------- attention softmax over S + coverage outputs + loss partials ----------------
__global__ void k_attn(const float* __restrict__ coverage, float* __restrict__ out) {
    int b = blockIdx.x, tid = threadIdx.x;  // 512 threads
    __shared__ float red[32];
    float e = (tid < S) ? g_energy[b*S + tid] : -1e30f;
    float m = blk_max(e, red);
    float ex = (tid < S) ? expf(e - m) : 0.f;
    float sum = blk_sum(ex, red);
    float part = 0.f;
    if (tid < S) {
        float a = ex / sum;
        out[OUT_ATTN + (size_t)b*S + tid] = a;
        float c = coverage[(size_t)b*S + tid];
        out[OUT_COV + (size_t)b*S + tid] = c + a;
        part = fminf(a, c);
    }
    float ps = blk_sum(part, red);
    if (tid == 0) g_covpart[b] = ps;
}

__global__ void k_loss(float* __restrict__ out) {
    __shared__ float red[32];
    float v = g_covpart[threadIdx.x];  // 512 threads == B
    float s = blk_sum(v, red);
    if (threadIdx.x == 0) out[OUT_LOSS] = s;
}

// ---------------- scatter: last-s-wins set semantics, added onto p_gen*p_vocab ----------------
__global__ void k_scatter(const int* __restrict__ enc_inputs, float* __restrict__ out) {
    int b = blockIdx.x, tid = threadIdx.x;  // 512 threads
    __shared__ int   sidx[S];
    __shared__ float sat[S];
    if (tid < S) {
        sidx[tid] = enc_inputs[(size_t)b*S + tid];
        sat[tid]  = out[OUT_ATTN + (size_t)b*S + tid];
    }
    __syncthreads();
    if (tid < S) {
        int v = sidx[tid];
        bool win = true;
        for (int s2 = tid + 1; s2 < S; s2++)
            if (sidx[s2] == v) { win = false; break; }
        if (win) {
            float g = g_pgen[b];
            size_t o = (size_t)b*V + v;
            out[o] += (1.f - g) * sat[tid];   // unique winner per (b,v): race-free RMW
        }
    }
}

// ---------------- host launcher ----------------
extern "C" void kernel_launch(void* const* d_in, const int* in_sizes, int n_in,
                              void* d_out, int out_size) {
    const float* coverage   = (const float*)d_in[0];
    const float* enc_out    = (const float*)d_in[1];
    const float* h0         = (const float*)d_in[2];
    const float* c0         = (const float*)d_in[3];
    const float* attn       = (const float*)d_in[4];
    const int*   dec_input  = (const int*)d_in[5];
    const int*   enc_inputs = (const int*)d_in[6];
    const float* emb_table  = (const float*)d_in[7];
    const float* W_ih       = (const float*)d_in[8];
    const float* W_hh       = (const float*)d_in[9];
    const float* b_ih       = (const float*)d_in[10];
    const float* b_hh       = (const float*)d_in[11];
    const float* awh_W      = (const float*)d_in[12];
    const float* awh_b      = (const float*)d_in[13];
    const float* aws_W      = (const float*)d_in[14];
    const float* aws_b      = (const float*)d_in[15];
    const float* awc        = (const float*)d_in[16];
    const float* av         = (const float*)d_in[17];
    const float* wh         = (const float*)d_in[18];
    const float* ws         = (const float*)d_in[19];
    const float* wx         = (const float*)d_in[20];
    const float* v_W        = (const float*)d_in[21];
    const float* v_b        = (const float*)d_in[22];
    float* out = (float*)d_out;

    float *p_xcat, *p_Wcat, *p_bcat, *p_gates, *p_whapp, *p_wsapp;
    cudaGetSymbolAddress((void**)&p_xcat,  g_xcat);
    cudaGetSymbolAddress((void**)&p_Wcat,  g_Wcat);
    cudaGetSymbolAddress((void**)&p_bcat,  g_bcat);
    cudaGetSymbolAddress((void**)&p_gates, g_gates);
    cudaGetSymbolAddress((void**)&p_whapp, g_whapp);
    cudaGetSymbolAddress((void**)&p_wsapp, g_wsapp);

    // context / embed / p_gen partials
    k_context<<<B, 256>>>(attn, enc_out, dec_input, emb_table, wh, wx);
    // pack for gates GEMM
    k_packw<<<(G4*KX + 255)/256, 256>>>(W_ih, W_hh, b_ih, b_hh);
    k_packx<<<(B*KX + 255)/256, 256>>>(h0);
    // gates = [context|embed|h0] @ [W_ih|W_hh]^T + (b_ih+b_hh)
    sgemm_bt<<<dim3(G4/128, B/128), 256>>>(p_xcat, p_Wcat, p_bcat, p_gates, B, G4, KX);
    // LSTM -> h_t, c_t (into d_out), p_gen
    k_lstm<<<B, 256>>>(c0, ws, out);
    // wh_app = enc_out @ awh_W^T + awh_b   (the big 53.7 GF GEMM)
    sgemm_bt<<<dim3(H/128, (B*S)/128), 256>>>(enc_out, awh_W, awh_b, p_whapp, B*S, H, E);
    // ws_app = h_t @ aws_W^T + aws_b
    sgemm_bt<<<dim3(H/128, B/128), 256>>>(out + OUT_HT, aws_W, aws_b, p_wsapp, B, H, H);
    // logits = h_t @ v_W^T + v_b  -> staged into d_out[0 : B*V]
    sgemm_bt<<<dim3((V + 127)/128, B/128), 256>>>(out + OUT_HT, v_W, v_b, out, B, V, H);
    // vocab softmax
    k_rowstats<<<B, 1024>>>(out);
    k_norm<<<(int)(((size_t)B*V + 255)/256), 256>>>(out);
    // attention energy -> softmax -> coverage outputs
    k_energy<<<dim3(S/8, B), 256>>>(coverage, awc, av);
    k_attn<<<B, 512>>>(coverage, out);
    k_loss<<<1, 512>>>(out);
    // pointer-generator scatter (after k_norm)
    k_scatter<<<B, 512>>>(enc_inputs, out);
}

// round 6
// speedup vs baseline: 1.7331x; 1.7324x over previous
#include <cuda_runtime.h>
#include <cuda_bf16.h>
#include <math.h>
#include <stdint.h>

#define B 512
#define S 400
#define V 50000
#define E 512
#define H 256
#define EMB 128
#define KX (E + EMB + H)
#define G4 (4*H)

#define OUT_COV    ((size_t)B*V)
#define OUT_HT     (OUT_COV  + (size_t)B*S)
#define OUT_CT     (OUT_HT   + (size_t)B*H)
#define OUT_ATTN   (OUT_CT   + (size_t)B*H)
#define OUT_LOSS   (OUT_ATTN + (size_t)B*S)

__device__ float g_context[B*E];
__device__ float g_embed[B*EMB];
__device__ float g_xcat[B*KX];
__device__ float g_Wcat[G4*KX];
__device__ float g_bcat[G4];
__device__ float g_gates[B*G4];
__device__ float g_cw[B];
__device__ float g_exw[B];
__device__ float g_pgen[B];
__device__ float g_wsapp[B*H];
__device__ float g_bias2[H];
__device__ float g_energy[B*S];
__device__ float g_covpart[B];
__device__ float g_rowmax[B];
__device__ float g_rowinv[B];

// ---------- helpers ----------
__device__ __forceinline__ uint32_t smem_u32(const void* p) {
    uint32_t a;
    asm("{ .reg .u64 t; cvta.to.shared.u64 t, %1; cvt.u32.u64 %0, t; }" : "=r"(a) : "l"(p));
    return a;
}
__device__ __forceinline__ void ldm_x4(uint32_t* r, uint32_t addr) {
    asm volatile("ldmatrix.sync.aligned.m8n8.x4.shared.b16 {%0,%1,%2,%3}, [%4];"
        : "=r"(r[0]), "=r"(r[1]), "=r"(r[2]), "=r"(r[3]) : "r"(addr));
}
__device__ __forceinline__ void mma16816(float* d, const uint32_t* a, const uint32_t* b) {
    asm volatile("mma.sync.aligned.m16n8k16.row.col.f32.bf16.bf16.f32 "
        "{%0,%1,%2,%3}, {%4,%5,%6,%7}, {%8,%9}, {%0,%1,%2,%3};"
        : "+f"(d[0]), "+f"(d[1]), "+f"(d[2]), "+f"(d[3])
        : "r"(a[0]), "r"(a[1]), "r"(a[2]), "r"(a[3]), "r"(b[0]), "r"(b[1]));
}
// fp32 -> bf16 hi/lo, padded layout: row stride 40 halves (80B), k multiple of 4
__device__ __forceinline__ void st_hilo(char* hiB, char* loB, int row, int k, float4 v) {
    int off = row*80 + k*2;
    __nv_bfloat16 h0 = __float2bfloat16(v.x), h1 = __float2bfloat16(v.y),
                  h2 = __float2bfloat16(v.z), h3 = __float2bfloat16(v.w);
    __nv_bfloat16 l0 = __float2bfloat16(v.x - __bfloat162float(h0)),
                  l1 = __float2bfloat16(v.y - __bfloat162float(h1)),
                  l2 = __float2bfloat16(v.z - __bfloat162float(h2)),
                  l3 = __float2bfloat16(v.w - __bfloat162float(h3));
    *(__nv_bfloat162*)(hiB + off)     = __halves2bfloat162(h0, h1);
    *(__nv_bfloat162*)(hiB + off + 4) = __halves2bfloat162(h2, h3);
    *(__nv_bfloat162*)(loB + off)     = __halves2bfloat162(l0, l1);
    *(__nv_bfloat162*)(loB + off + 4) = __halves2bfloat162(l2, l3);
}
// one k16 step for a 32x64 warp tile: 3-term bf16 (hh + hl + lh)
__device__ __forceinline__ void mma_step(float acc[2][8][4],
    uint32_t aHa, uint32_t aLa, uint32_t bHa, uint32_t bLa) {
    uint32_t aH[2][4], aL[2][4], bH[4][4], bL[4][4];
    #pragma unroll
    for (int mt = 0; mt < 2; mt++) { ldm_x4(aH[mt], aHa + mt*1280); ldm_x4(aL[mt], aLa + mt*1280); }
    #pragma unroll
    for (int np = 0; np < 4; np++) { ldm_x4(bH[np], bHa + np*1280); ldm_x4(bL[np], bLa + np*1280); }
    #pragma unroll
    for (int mt = 0; mt < 2; mt++)
        #pragma unroll
        for (int np = 0; np < 4; np++) {
            mma16816(acc[mt][2*np],   aH[mt], bH[np]);
            mma16816(acc[mt][2*np+1], aH[mt], bH[np]+2);
            mma16816(acc[mt][2*np],   aH[mt], bL[np]);
            mma16816(acc[mt][2*np+1], aH[mt], bL[np]+2);
            mma16816(acc[mt][2*np],   aL[mt], bH[np]);
            mma16816(acc[mt][2*np+1], aL[mt], bH[np]+2);
        }
}

__device__ __forceinline__ float sigmoidf_(float x) { return 1.f / (1.f + expf(-x)); }

__device__ __forceinline__ float blk_sum(float v, float* red) {
    int tid = threadIdx.x;
    #pragma unroll
    for (int o = 16; o; o >>= 1) v += __shfl_down_sync(0xffffffffu, v, o);
    if ((tid & 31) == 0) red[tid >> 5] = v;
    __syncthreads();
    float r;
    if (tid < 32) {
        int nw = (blockDim.x + 31) >> 5;
        r = (tid < nw) ? red[tid] : 0.f;
        #pragma unroll
        for (int o = 16; o; o >>= 1) r += __shfl_down_sync(0xffffffffu, r, o);
        if (tid == 0) red[0] = r;
    }
    __syncthreads();
    r = red[0];
    __syncthreads();
    return r;
}
__device__ __forceinline__ float blk_max(float v, float* red) {
    int tid = threadIdx.x;
    #pragma unroll
    for (int o = 16; o; o >>= 1) v = fmaxf(v, __shfl_down_sync(0xffffffffu, v, o));
    if ((tid & 31) == 0) red[tid >> 5] = v;
    __syncthreads();
    float r;
    if (tid < 32) {
        int nw = (blockDim.x + 31) >> 5;
        r = (tid < nw) ? red[tid] : -1e30f;
        #pragma unroll
        for (int o = 16; o; o >>= 1) r = fmaxf(r, __shfl_down_sync(0xffffffffu, r, o));
        if (tid == 0) red[0] = r;
    }
    __syncthreads();
    r = red[0];
    __syncthreads();
    return r;
}

// ---------- context, embed, p_gen partials ----------
__global__ void k_context(const float* __restrict__ attn, const float* __restrict__ enc_out,
                          const int* __restrict__ dec_input, const float* __restrict__ emb_table,
                          const float* __restrict__ wh, const float* __restrict__ wx) {
    int b = blockIdx.x, tid = threadIdx.x;
    __shared__ float sa[S];
    __shared__ float red[32];
    for (int s = tid; s < S; s += 256) sa[s] = attn[(size_t)b*S + s];
    __syncthreads();
    const float* eb = enc_out + (size_t)b*S*E;
    float a0 = 0.f, a1 = 0.f;
    #pragma unroll 4
    for (int s = 0; s < S; s++) {
        float a = sa[s];
        a0 += a * eb[(size_t)s*E + tid];
        a1 += a * eb[(size_t)s*E + 256 + tid];
    }
    g_context[b*E + tid]       = a0;
    g_context[b*E + 256 + tid] = a1;
    float cw = blk_sum(a0*wh[tid] + a1*wh[256+tid], red);
    if (tid == 0) g_cw[b] = cw;
    float ew = 0.f;
    if (tid < EMB) {
        float e = emb_table[(size_t)dec_input[b]*EMB + tid];
        g_embed[b*EMB + tid] = e;
        ew = e * wx[tid];
    }
    float exw = blk_sum(ew, red);
    if (tid == 0) g_exw[b] = exw;
}

__global__ void k_packw(const float* __restrict__ W_ih, const float* __restrict__ W_hh,
                        const float* __restrict__ b_ih, const float* __restrict__ b_hh) {
    int idx = blockIdx.x*blockDim.x + threadIdx.x;
    if (idx < G4*KX) {
        int n = idx / KX, k = idx % KX;
        g_Wcat[idx] = (k < E+EMB) ? W_ih[(size_t)n*(E+EMB) + k] : W_hh[(size_t)n*H + (k - (E+EMB))];
    }
    if (idx < G4) g_bcat[idx] = b_ih[idx] + b_hh[idx];
}
__global__ void k_packx(const float* __restrict__ h0) {
    int idx = blockIdx.x*blockDim.x + threadIdx.x;
    if (idx < B*KX) {
        int b = idx / KX, k = idx % KX;
        float v;
        if (k < E)          v = g_context[b*E + k];
        else if (k < E+EMB) v = g_embed[b*EMB + (k - E)];
        else                v = h0[b*H + (k - E - EMB)];
        g_xcat[idx] = v;
    }
}
__global__ void k_bias2(const float* __restrict__ aws_b, const float* __restrict__ awh_b) {
    g_bias2[threadIdx.x] = aws_b[threadIdx.x] + awh_b[threadIdx.x];
}

// ---------- generic HMMA GEMM: tile 128x128, K-chunk 32, 256 threads ----------
// C[m,n] = bias[n] + sum_k A[m,k]*W[n,k].  M=512 fixed (grid.y=4), K % 32 == 0.
__global__ void hgemm(const float* __restrict__ A, const float* __restrict__ W,
                      const float* __restrict__ bias, float* __restrict__ C,
                      int N, int K) {
    __shared__ __align__(16) char sm[40960];  // AH 0, AL 10240, WH 20480, WL 30720
    char* AHc = sm;       char* ALc = sm + 10240;
    char* WHc = sm + 20480; char* WLc = sm + 30720;
    uint32_t sb = smem_u32(sm);
    uint32_t AH = sb, AL = sb + 10240, WH = sb + 20480, WL = sb + 30720;

    int tid = threadIdx.x, wid = tid >> 5, lane = tid & 31;
    int m0 = blockIdx.y * 128, n0 = blockIdx.x * 128;
    int wr = (wid & 3) * 32, wc = (wid >> 2) * 64;
    int lr = lane & 7, sect = lane >> 3;
    uint32_t aoff = (uint32_t)((wr + (sect & 1)*8 + lr)*80 + (sect >> 1)*16);
    uint32_t boff = (uint32_t)((wc + (sect >> 1)*8 + lr)*80 + (sect & 1)*16);

    float acc[2][8][4];
    #pragma unroll
    for (int i = 0; i < 2; i++)
        #pragma unroll
        for (int j = 0; j < 8; j++)
            #pragma unroll
            for (int e = 0; e < 4; e++) acc[i][j][e] = 0.f;

    for (int kc = 0; kc < K; kc += 32) {
        {   // A: row tid>>1, 16 floats at (tid&1)*16
            int r = tid >> 1, kb = (tid & 1) * 16;
            const float4* src = (const float4*)(A + (size_t)(m0 + r)*K + kc + kb);
            #pragma unroll
            for (int i = 0; i < 4; i++) st_hilo(AHc, ALc, r, kb + i*4, src[i]);
        }
        {   // W: row n0 + (tid>>1), zero-pad past N
            int r = tid >> 1, kb = (tid & 1) * 16;
            int n = n0 + r;
            #pragma unroll
            for (int i = 0; i < 4; i++) {
                float4 v = make_float4(0.f, 0.f, 0.f, 0.f);
                if (n < N) v = *(const float4*)(W + (size_t)n*K + kc + kb + i*4);
                st_hilo(WHc, WLc, r, kb + i*4, v);
            }
        }
        __syncthreads();
        #pragma unroll
        for (int ks = 0; ks < 64; ks += 32)
            mma_step(acc, AH + aoff + ks, AL + aoff + ks, WH + boff + ks, WL + boff + ks);
        __syncthreads();
    }

    int gid = lane >> 2, t4 = lane & 3;
    #pragma unroll
    for (int mt = 0; mt < 2; mt++)
        #pragma unroll
        for (int eh = 0; eh < 2; eh++) {
            size_t row = (size_t)(m0 + wr + mt*16 + eh*8 + gid);
            #pragma unroll
            for (int nt = 0; nt < 8; nt++) {
                int col = n0 + wc + nt*8 + 2*t4;
                if (col + 1 < N) {
                    float2 v;
                    v.x = acc[mt][nt][eh*2+0] + bias[col];
                    v.y = acc[mt][nt][eh*2+1] + bias[col+1];
                    *(float2*)&C[row*(size_t)N + col] = v;
                } else if (col < N) {
                    C[row*(size_t)N + col] = acc[mt][nt][eh*2] + bias[col];
                }
            }
        }
}

// ---------- fused wh_app GEMM + energy: tile 64x256, K=512 ----------
#define FK_SMEM 56576
__global__ void fk_whenergy(const float* __restrict__ A, const float* __restrict__ Wt,
                            const float* __restrict__ coverage,
                            const float* __restrict__ awc, const float* __restrict__ av) {
    extern __shared__ __align__(16) char sm[];
    char* WHc = sm;          char* WLc = sm + 20480;
    char* AHc = sm + 40960;  char* ALc = sm + 46080;
    float* swsA = (float*)(sm + 51200);
    float* swsB = (float*)(sm + 52224);
    float* sawc = (float*)(sm + 53248);
    float* sav  = (float*)(sm + 54272);
    float* scov = (float*)(sm + 55296);
    float* sred = (float*)(sm + 55552);
    uint32_t sb = smem_u32(sm);
    uint32_t WH = sb, WL = sb + 20480, AH = sb + 40960, AL = sb + 46080;

    int tid = threadIdx.x, wid = tid >> 5, lane = tid & 31;
    int m0 = blockIdx.x * 64;
    int b0 = m0 / S;
    int b1 = (b0 + 1 < B) ? b0 + 1 : b0;
    int bswitch = (b0 + 1) * S - m0;      // rows >= bswitch belong to b1
    int wr = (wid & 1) * 32, wc = (wid >> 1) * 64;
    int lr = lane & 7, sect = lane >> 3;
    uint32_t aoff = (uint32_t)((wr + (sect & 1)*8 + lr)*80 + (sect >> 1)*16);
    uint32_t boff = (uint32_t)((wc + (sect >> 1)*8 + lr)*80 + (sect & 1)*16);

    swsA[tid] = g_wsapp[b0*H + tid];
    swsB[tid] = g_wsapp[b1*H + tid];
    sawc[tid] = awc[tid];
    sav[tid]  = av[tid];
    if (tid < 64) scov[tid] = coverage[(size_t)m0 + tid];

    float acc[2][8][4];
    #pragma unroll
    for (int i = 0; i < 2; i++)
        #pragma unroll
        for (int j = 0; j < 8; j++)
            #pragma unroll
            for (int e = 0; e < 4; e++) acc[i][j][e] = 0.f;

    for (int kc = 0; kc < E; kc += 32) {
        {   // A: 64 rows, row = tid>>2, 8 floats at (tid&3)*8
            int r = tid >> 2, kb = (tid & 3) * 8;
            const float4* src = (const float4*)(A + (size_t)(m0 + r)*E + kc + kb);
            st_hilo(AHc, ALc, r, kb,     src[0]);
            st_hilo(AHc, ALc, r, kb + 4, src[1]);
        }
        {   // W: 256 rows, row = tid, 32 floats
            const float4* src = (const float4*)(Wt + (size_t)tid*E + kc);
            #pragma unroll
            for (int i = 0; i < 8; i++) st_hilo(WHc, WLc, tid, i*4, src[i]);
        }
        __syncthreads();
        #pragma unroll
        for (int ks = 0; ks < 64; ks += 32)
            mma_step(acc, AH + aoff + ks, AL + aoff + ks, WH + boff + ks, WL + boff + ks);
        __syncthreads();
    }

    // energy epilogue on register accumulators
    int gid = lane >> 2, t4 = lane & 3;
    #pragma unroll
    for (int mt = 0; mt < 2; mt++)
        #pragma unroll
        for (int eh = 0; eh < 2; eh++) {
            int row = wr + mt*16 + eh*8 + gid;
            float c = scov[row];
            const float* sws = (row < bswitch) ? swsA : swsB;
            float p = 0.f;
            #pragma unroll
            for (int nt = 0; nt < 8; nt++)
                #pragma unroll
                for (int e2 = 0; e2 < 2; e2++) {
                    int h = wc + nt*8 + 2*t4 + e2;
                    float x = acc[mt][nt][eh*2 + e2] + sws[h] + c * sawc[h];
                    p += tanhf(x) * sav[h];
                }
            p += __shfl_xor_sync(0xffffffffu, p, 1);
            p += __shfl_xor_sync(0xffffffffu, p, 2);
            if (t4 == 0) sred[row*4 + (wid >> 1)] = p;
        }
    __syncthreads();
    if (tid < 64)
        g_energy[(size_t)m0 + tid] = sred[tid*4] + sred[tid*4+1] + sred[tid*4+2] + sred[tid*4+3];
}

// ---------- LSTM + p_gen ----------
__global__ void k_lstm(const float* __restrict__ c0, const float* __restrict__ ws,
                       float* __restrict__ out) {
    int b = blockIdx.x, h = threadIdx.x;
    __shared__ float red[32];
    const float* g = g_gates + (size_t)b*G4;
    float ig = sigmoidf_(g[h]);
    float fg = sigmoidf_(g[H + h]);
    float gg = tanhf(g[2*H + h]);
    float og = sigmoidf_(g[3*H + h]);
    float c  = fg * c0[b*H + h] + ig * gg;
    float ht = og * tanhf(c);
    out[OUT_CT + (size_t)b*H + h] = c;
    out[OUT_HT + (size_t)b*H + h] = ht;
    float hw = blk_sum(ht * ws[h], red);
    if (h == 0) g_pgen[b] = sigmoidf_(g_cw[b] + hw + g_exw[b]);
}

// ---------- vocab softmax ----------
__global__ void k_rowstats(const float* __restrict__ out) {
    int b = blockIdx.x, tid = threadIdx.x;
    const float* row = out + (size_t)b*V;
    float m = -1e30f, s = 0.f;
    for (int v = tid; v < V; v += 1024) {
        float x = row[v];
        if (x > m) { s = s*expf(m - x) + 1.f; m = x; }
        else       { s += expf(x - m); }
    }
    __shared__ float sm_[1024], ss[1024];
    sm_[tid] = m; ss[tid] = s;
    __syncthreads();
    for (int off = 512; off; off >>= 1) {
        if (tid < off) {
            float m2 = sm_[tid+off], s2 = ss[tid+off];
            float M = fmaxf(sm_[tid], m2);
            ss[tid] = ss[tid]*expf(sm_[tid] - M) + s2*expf(m2 - M);
            sm_[tid] = M;
        }
        __syncthreads();
    }
    if (tid == 0) { g_rowmax[b] = sm_[0]; g_rowinv[b] = 1.f/ss[0]; }
}
__global__ void k_norm(float* __restrict__ out) {
    size_t idx = (size_t)blockIdx.x*blockDim.x + threadIdx.x;
    if (idx < (size_t)B*V) {
        int b = (int)(idx / V);
        out[idx] = g_pgen[b] * expf(out[idx] - g_rowmax[b]) * g_rowinv[b];
    }
}

// ---------- attention softmax + coverage + loss ----------
__global__ void k_attn(const float* __restrict__ coverage, float* __restrict__ out) {
    int b = blockIdx.x, tid = threadIdx.x;
    __shared__ float red[32];
    float e = (tid < S) ? g_energy[b*S + tid] : -1e30f;
    float m = blk_max(e, red);
    float ex = (tid < S) ? expf(e - m) : 0.f;
    float sum = blk_sum(ex, red);
    float part = 0.f;
    if (tid < S) {
        float a = ex / sum;
        out[OUT_ATTN + (size_t)b*S + tid] = a;
        float c = coverage[(size_t)b*S + tid];
        out[OUT_COV + (size_t)b*S + tid] = c + a;
        part = fminf(a, c);
    }
    float ps = blk_sum(part, red);
    if (tid == 0) g_covpart[b] = ps;
}
__global__ void k_loss(float* __restrict__ out) {
    __shared__ float red[32];
    float s = blk_sum(g_covpart[threadIdx.x], red);
    if (threadIdx.x == 0) out[OUT_LOSS] = s;
}

// ---------- scatter ----------
__global__ void k_scatter(const int* __restrict__ enc_inputs, float* __restrict__ out) {
    int b = blockIdx.x, tid = threadIdx.x;
    __shared__ int   sidx[S];
    __shared__ float sat[S];
    if (tid < S) {
        sidx[tid] = enc_inputs[(size_t)b*S + tid];
        sat[tid]  = out[OUT_ATTN + (size_t)b*S + tid];
    }
    __syncthreads();
    if (tid < S) {
        int v = sidx[tid];
        bool win = true;
        for (int s2 = tid + 1; s2 < S; s2++)
            if (sidx[s2] == v) { win = false; break; }
        if (win) out[(size_t)b*V + v] += (1.f - g_pgen[b]) * sat[tid];
    }
}

// ---------- host ----------
extern "C" void kernel_launch(void* const* d_in, const int* in_sizes, int n_in,
                              void* d_out, int out_size) {
    const float* coverage   = (const float*)d_in[0];
    const float* enc_out    = (const float*)d_in[1];
    const float* h0         = (const float*)d_in[2];
    const float* c0         = (const float*)d_in[3];
    const float* attn       = (const float*)d_in[4];
    const int*   dec_input  = (const int*)d_in[5];
    const int*   enc_inputs = (const int*)d_in[6];
    const float* emb_table  = (const float*)d_in[7];
    const float* W_ih       = (const float*)d_in[8];
    const float* W_hh       = (const float*)d_in[9];
    const float* b_ih       = (const float*)d_in[10];
    const float* b_hh       = (const float*)d_in[11];
    const float* awh_W      = (const float*)d_in[12];
    const float* awh_b      = (const float*)d_in[13];
    const float* aws_W      = (const float*)d_in[14];
    const float* aws_b      = (const float*)d_in[15];
    const float* awc        = (const float*)d_in[16];
    const float* av         = (const float*)d_in[17];
    const float* wh         = (const float*)d_in[18];
    const float* ws         = (const float*)d_in[19];
    const float* wx         = (const float*)d_in[20];
    const float* v_W        = (const float*)d_in[21];
    const float* v_b        = (const float*)d_in[22];
    float* out = (float*)d_out;

    float *p_xcat, *p_Wcat, *p_bcat, *p_gates, *p_wsapp, *p_bias2;
    cudaGetSymbolAddress((void**)&p_xcat,  g_xcat);
    cudaGetSymbolAddress((void**)&p_Wcat,  g_Wcat);
    cudaGetSymbolAddress((void**)&p_bcat,  g_bcat);
    cudaGetSymbolAddress((void**)&p_gates, g_gates);
    cudaGetSymbolAddress((void**)&p_wsapp, g_wsapp);
    cudaGetSymbolAddress((void**)&p_bias2, g_bias2);

    cudaFuncSetAttribute(fk_whenergy, cudaFuncAttributeMaxDynamicSharedMemorySize, FK_SMEM);

    k_context<<<B, 256>>>(attn, enc_out, dec_input, emb_table, wh, wx);
    k_packw<<<(G4*KX + 255)/256, 256>>>(W_ih, W_hh, b_ih, b_hh);
    k_packx<<<(B*KX + 255)/256, 256>>>(h0);
    k_bias2<<<1, H>>>(aws_b, awh_b);
    // gates = xcat @ Wcat^T + bcat
    hgemm<<<dim3(G4/128, B/128), 256>>>(p_xcat, p_Wcat, p_bcat, p_gates, G4, KX);
    k_lstm<<<B, 256>>>(c0, ws, out);
    // ws_app_eff = h_t @ aws_W^T + (aws_b + awh_b)
    hgemm<<<dim3(H/128, B/128), 256>>>(out + OUT_HT, aws_W, p_bias2, p_wsapp, H, H);
    // fused wh_app GEMM + energy
    fk_whenergy<<<(B*S)/64, 256, FK_SMEM>>>(enc_out, awh_W, coverage, awc, av);
    // logits = h_t @ v_W^T + v_b
    hgemm<<<dim3((V + 127)/128, B/128), 256>>>(out + OUT_HT, v_W, v_b, out, V, H);
    k_rowstats<<<B, 1024>>>(out);
    k_norm<<<(int)(((size_t)B*V + 255)/256), 256>>>(out);
    k_attn<<<B, 512>>>(coverage, out);
    k_loss<<<1, B>>>(out);
    k_scatter<<<B, 512>>>(enc_inputs, out);
}

// round 7
// speedup vs baseline: 1.7861x; 1.0306x over previous
#include <cuda_runtime.h>
#include <cuda_bf16.h>
#include <math.h>
#include <stdint.h>

#define B 512
#define S 400
#define V 50000
#define E 512
#define H 256
#define EMB 128
#define KX (E + EMB + H)
#define G4 (4*H)

#define OUT_COV    ((size_t)B*V)
#define OUT_HT     (OUT_COV  + (size_t)B*S)
#define OUT_CT     (OUT_HT   + (size_t)B*H)
#define OUT_ATTN   (OUT_CT   + (size_t)B*H)
#define OUT_LOSS   (OUT_ATTN + (size_t)B*S)

__device__ float g_ctxp[2][B*E];
__device__ float g_embed[B*EMB];
__device__ float g_bcat[G4];
__device__ float g_gates[B*G4];
__device__ float g_cwp[2*B];
__device__ float g_exw[B];
__device__ float g_pgen[B];
__device__ float g_wsapp[B*H];
__device__ float g_bias2[H];
__device__ float g_energy[B*S];
__device__ float g_covpart[B];
__device__ float g_rowmax[B];
__device__ float g_rowinv[B];

// bf16 hi/lo pre-converted operands
__device__ __nv_bfloat16 g_WcatH[G4*KX], g_WcatL[G4*KX];
__device__ __nv_bfloat16 g_xcatH[B*KX],  g_xcatL[B*KX];
__device__ __nv_bfloat16 g_awhH[H*E],    g_awhL[H*E];
__device__ __nv_bfloat16 g_awsH[H*H],    g_awsL[H*H];
__device__ __nv_bfloat16 g_vWH[(size_t)V*H], g_vWL[(size_t)V*H];
__device__ __nv_bfloat16 g_htH[B*H],     g_htL[B*H];

// ---------- helpers ----------
__device__ __forceinline__ uint32_t smem_u32(const void* p) {
    uint32_t a;
    asm("{ .reg .u64 t; cvta.to.shared.u64 t, %1; cvt.u32.u64 %0, t; }" : "=r"(a) : "l"(p));
    return a;
}
__device__ __forceinline__ void ldm_x4(uint32_t* r, uint32_t addr) {
    asm volatile("ldmatrix.sync.aligned.m8n8.x4.shared.b16 {%0,%1,%2,%3}, [%4];"
        : "=r"(r[0]), "=r"(r[1]), "=r"(r[2]), "=r"(r[3]) : "r"(addr));
}
__device__ __forceinline__ void mma16816(float* d, const uint32_t* a, const uint32_t* b) {
    asm volatile("mma.sync.aligned.m16n8k16.row.col.f32.bf16.bf16.f32 "
        "{%0,%1,%2,%3}, {%4,%5,%6,%7}, {%8,%9}, {%0,%1,%2,%3};"
        : "+f"(d[0]), "+f"(d[1]), "+f"(d[2]), "+f"(d[3])
        : "r"(a[0]), "r"(a[1]), "r"(a[2]), "r"(a[3]), "r"(b[0]), "r"(b[1]));
}
// fp32 -> bf16 hi/lo into padded smem (row stride 80B, k in [0,32))
__device__ __forceinline__ void st_hilo(char* hiB, char* loB, int row, int k, float4 v) {
    int off = row*80 + k*2;
    __nv_bfloat16 h0 = __float2bfloat16(v.x), h1 = __float2bfloat16(v.y),
                  h2 = __float2bfloat16(v.z), h3 = __float2bfloat16(v.w);
    __nv_bfloat16 l0 = __float2bfloat16(v.x - __bfloat162float(h0)),
                  l1 = __float2bfloat16(v.y - __bfloat162float(h1)),
                  l2 = __float2bfloat16(v.z - __bfloat162float(h2)),
                  l3 = __float2bfloat16(v.w - __bfloat162float(h3));
    *(__nv_bfloat162*)(hiB + off)     = __halves2bfloat162(h0, h1);
    *(__nv_bfloat162*)(hiB + off + 4) = __halves2bfloat162(h2, h3);
    *(__nv_bfloat162*)(loB + off)     = __halves2bfloat162(l0, l1);
    *(__nv_bfloat162*)(loB + off + 4) = __halves2bfloat162(l2, l3);
}
__device__ __forceinline__ void split2(float v, __nv_bfloat16* hp, __nv_bfloat16* lp) {
    __nv_bfloat16 h = __float2bfloat16(v);
    *hp = h;
    *lp = __float2bfloat16(v - __bfloat162float(h));
}
// one k16-pair step (32 k) for a 32x64 warp tile: 3-term bf16
__device__ __forceinline__ void mma_step(float acc[2][8][4],
    uint32_t aHa, uint32_t aLa, uint32_t bHa, uint32_t bLa) {
    uint32_t aH[2][4], aL[2][4], bH[4][4], bL[4][4];
    #pragma unroll
    for (int mt = 0; mt < 2; mt++) { ldm_x4(aH[mt], aHa + mt*1280); ldm_x4(aL[mt], aLa + mt*1280); }
    #pragma unroll
    for (int np = 0; np < 4; np++) { ldm_x4(bH[np], bHa + np*1280); ldm_x4(bL[np], bLa + np*1280); }
    #pragma unroll
    for (int mt = 0; mt < 2; mt++)
        #pragma unroll
        for (int np = 0; np < 4; np++) {
            mma16816(acc[mt][2*np],   aH[mt], bH[np]);
            mma16816(acc[mt][2*np+1], aH[mt], bH[np]+2);
            mma16816(acc[mt][2*np],   aH[mt], bL[np]);
            mma16816(acc[mt][2*np+1], aH[mt], bL[np]+2);
            mma16816(acc[mt][2*np],   aL[mt], bH[np]);
            mma16816(acc[mt][2*np+1], aL[mt], bH[np]+2);
        }
}

__device__ __forceinline__ float sigmoidf_(float x) { return 1.f / (1.f + expf(-x)); }

__device__ __forceinline__ float blk_sum(float v, float* red) {
    int tid = threadIdx.x;
    #pragma unroll
    for (int o = 16; o; o >>= 1) v += __shfl_down_sync(0xffffffffu, v, o);
    if ((tid & 31) == 0) red[tid >> 5] = v;
    __syncthreads();
    float r;
    if (tid < 32) {
        int nw = (blockDim.x + 31) >> 5;
        r = (tid < nw) ? red[tid] : 0.f;
        #pragma unroll
        for (int o = 16; o; o >>= 1) r += __shfl_down_sync(0xffffffffu, r, o);
        if (tid == 0) red[0] = r;
    }
    __syncthreads();
    r = red[0];
    __syncthreads();
    return r;
}
__device__ __forceinline__ float blk_max(float v, float* red) {
    int tid = threadIdx.x;
    #pragma unroll
    for (int o = 16; o; o >>= 1) v = fmaxf(v, __shfl_down_sync(0xffffffffu, v, o));
    if ((tid & 31) == 0) red[tid >> 5] = v;
    __syncthreads();
    float r;
    if (tid < 32) {
        int nw = (blockDim.x + 31) >> 5;
        r = (tid < nw) ? red[tid] : -1e30f;
        #pragma unroll
        for (int o = 16; o; o >>= 1) r = fmaxf(r, __shfl_down_sync(0xffffffffu, r, o));
        if (tid == 0) red[0] = r;
    }
    __syncthreads();
    r = red[0];
    __syncthreads();
    return r;
}

// ---------- generic fp32 -> bf16 hi/lo converter (n % 4 == 0) ----------
__global__ void k_cvt(const float* __restrict__ src, __nv_bfloat16* __restrict__ hi,
                      __nv_bfloat16* __restrict__ lo, int n) {
    int idx = (blockIdx.x*blockDim.x + threadIdx.x) * 4;
    if (idx < n) {
        float4 v = *(const float4*)(src + idx);
        __nv_bfloat16 h0, h1, h2, h3, l0, l1, l2, l3;
        split2(v.x, &h0, &l0); split2(v.y, &h1, &l1);
        split2(v.z, &h2, &l2); split2(v.w, &h3, &l3);
        *(__nv_bfloat162*)(hi + idx)     = __halves2bfloat162(h0, h1);
        *(__nv_bfloat162*)(hi + idx + 2) = __halves2bfloat162(h2, h3);
        *(__nv_bfloat162*)(lo + idx)     = __halves2bfloat162(l0, l1);
        *(__nv_bfloat162*)(lo + idx + 2) = __halves2bfloat162(l2, l3);
    }
}

// ---------- context (split over S halves), embed, p_gen partials ----------
__global__ void k_context(const float* __restrict__ attn, const float* __restrict__ enc_out,
                          const int* __restrict__ dec_input, const float* __restrict__ emb_table,
                          const float* __restrict__ wh, const float* __restrict__ wx) {
    int b = blockIdx.x, half = blockIdx.y, tid = threadIdx.x;
    __shared__ float sa[S/2];
    __shared__ float red[32];
    int s0 = half * (S/2);
    for (int s = tid; s < S/2; s += 256) sa[s] = attn[(size_t)b*S + s0 + s];
    __syncthreads();
    const float* eb = enc_out + ((size_t)b*S + s0)*E;
    float a0 = 0.f, a1 = 0.f;
    #pragma unroll 4
    for (int s = 0; s < S/2; s++) {
        float a = sa[s];
        a0 += a * eb[(size_t)s*E + tid];
        a1 += a * eb[(size_t)s*E + 256 + tid];
    }
    g_ctxp[half][b*E + tid]       = a0;
    g_ctxp[half][b*E + 256 + tid] = a1;
    float cw = blk_sum(a0*wh[tid] + a1*wh[256+tid], red);
    if (tid == 0) g_cwp[half*B + b] = cw;
    if (half == 0) {
        float ew = 0.f;
        if (tid < EMB) {
            float e = emb_table[(size_t)dec_input[b]*EMB + tid];
            g_embed[b*EMB + tid] = e;
            ew = e * wx[tid];
        }
        float exw = blk_sum(ew, red);
        if (tid == 0) g_exw[b] = exw;
    }
}

__global__ void k_packw(const float* __restrict__ W_ih, const float* __restrict__ W_hh,
                        const float* __restrict__ b_ih, const float* __restrict__ b_hh) {
    int idx = blockIdx.x*blockDim.x + threadIdx.x;
    if (idx < G4*KX) {
        int n = idx / KX, k = idx % KX;
        float w = (k < E+EMB) ? W_ih[(size_t)n*(E+EMB) + k] : W_hh[(size_t)n*H + (k - (E+EMB))];
        split2(w, &g_WcatH[idx], &g_WcatL[idx]);
    }
    if (idx < G4) g_bcat[idx] = b_ih[idx] + b_hh[idx];
}
__global__ void k_packx(const float* __restrict__ h0) {
    int idx = blockIdx.x*blockDim.x + threadIdx.x;
    if (idx < B*KX) {
        int b = idx / KX, k = idx % KX;
        float v;
        if (k < E)          v = g_ctxp[0][b*E + k] + g_ctxp[1][b*E + k];
        else if (k < E+EMB) v = g_embed[b*EMB + (k - E)];
        else                v = h0[b*H + (k - E - EMB)];
        split2(v, &g_xcatH[idx], &g_xcatL[idx]);
    }
}
__global__ void k_bias2(const float* __restrict__ aws_b, const float* __restrict__ awh_b) {
    g_bias2[threadIdx.x] = aws_b[threadIdx.x] + awh_b[threadIdx.x];
}

// ---------- HMMA GEMM on pre-split bf16: tile 128x128, K-chunk 32, M=512 ----------
__global__ void hgemm(const __nv_bfloat16* __restrict__ Ah, const __nv_bfloat16* __restrict__ Al,
                      const __nv_bfloat16* __restrict__ Wh, const __nv_bfloat16* __restrict__ Wl,
                      const float* __restrict__ bias, float* __restrict__ C,
                      int N, int K) {
    __shared__ __align__(16) char sm[40960];
    char* AHc = sm;         char* ALc = sm + 10240;
    char* WHc = sm + 20480; char* WLc = sm + 30720;
    uint32_t sb = smem_u32(sm);
    uint32_t AH = sb, AL = sb + 10240, WH = sb + 20480, WL = sb + 30720;

    int tid = threadIdx.x, wid = tid >> 5, lane = tid & 31;
    int m0 = blockIdx.y * 128, n0 = blockIdx.x * 128;
    int wr = (wid & 3) * 32, wc = (wid >> 2) * 64;
    int lr = lane & 7, sect = lane >> 3;
    uint32_t aoff = (uint32_t)((wr + (sect & 1)*8 + lr)*80 + (sect >> 1)*16);
    uint32_t boff = (uint32_t)((wc + (sect >> 1)*8 + lr)*80 + (sect & 1)*16);

    float acc[2][8][4];
    #pragma unroll
    for (int i = 0; i < 2; i++)
        #pragma unroll
        for (int j = 0; j < 8; j++)
            #pragma unroll
            for (int e = 0; e < 4; e++) acc[i][j][e] = 0.f;

    int r = tid >> 1, kb = (tid & 1) * 16;
    int off = r*80 + kb*2;
    for (int kc = 0; kc < K; kc += 32) {
        {
            const uint4* sH = (const uint4*)(Ah + (size_t)(m0 + r)*K + kc + kb);
            const uint4* sL = (const uint4*)(Al + (size_t)(m0 + r)*K + kc + kb);
            uint4 h0 = sH[0], h1 = sH[1], l0 = sL[0], l1 = sL[1];
            *(uint4*)(AHc + off) = h0; *(uint4*)(AHc + off + 16) = h1;
            *(uint4*)(ALc + off) = l0; *(uint4*)(ALc + off + 16) = l1;
        }
        {
            int n = n0 + r;
            uint4 z = make_uint4(0,0,0,0);
            uint4 h0 = z, h1 = z, l0 = z, l1 = z;
            if (n < N) {
                const uint4* sH = (const uint4*)(Wh + (size_t)n*K + kc + kb);
                const uint4* sL = (const uint4*)(Wl + (size_t)n*K + kc + kb);
                h0 = sH[0]; h1 = sH[1]; l0 = sL[0]; l1 = sL[1];
            }
            *(uint4*)(WHc + off) = h0; *(uint4*)(WHc + off + 16) = h1;
            *(uint4*)(WLc + off) = l0; *(uint4*)(WLc + off + 16) = l1;
        }
        __syncthreads();
        #pragma unroll
        for (int ks = 0; ks < 64; ks += 32)
            mma_step(acc, AH + aoff + ks, AL + aoff + ks, WH + boff + ks, WL + boff + ks);
        __syncthreads();
    }

    int gid = lane >> 2, t4 = lane & 3;
    #pragma unroll
    for (int mt = 0; mt < 2; mt++)
        #pragma unroll
        for (int eh = 0; eh < 2; eh++) {
            size_t row = (size_t)(m0 + wr + mt*16 + eh*8 + gid);
            #pragma unroll
            for (int nt = 0; nt < 8; nt++) {
                int col = n0 + wc + nt*8 + 2*t4;
                if (col + 1 < N) {
                    float2 v;
                    v.x = acc[mt][nt][eh*2+0] + bias[col];
                    v.y = acc[mt][nt][eh*2+1] + bias[col+1];
                    *(float2*)&C[row*(size_t)N + col] = v;
                } else if (col < N) {
                    C[row*(size_t)N + col] = acc[mt][nt][eh*2] + bias[col];
                }
            }
        }
}

// ---------- fused wh_app GEMM + energy: tile 64x256, K=512, W pre-split bf16 ----------
#define FK_SMEM 56576
__global__ void fk_whenergy(const float* __restrict__ A,
                            const __nv_bfloat16* __restrict__ Wh, const __nv_bfloat16* __restrict__ Wl,
                            const float* __restrict__ coverage,
                            const float* __restrict__ awc, const float* __restrict__ av) {
    extern __shared__ __align__(16) char sm[];
    char* WHc = sm;          char* WLc = sm + 20480;
    char* AHc = sm + 40960;  char* ALc = sm + 46080;
    float* swsA = (float*)(sm + 51200);
    float* swsB = (float*)(sm + 52224);
    float* sawc = (float*)(sm + 53248);
    float* sav  = (float*)(sm + 54272);
    float* scov = (float*)(sm + 55296);
    float* sred = (float*)(sm + 55552);
    uint32_t sb = smem_u32(sm);
    uint32_t WH = sb, WL = sb + 20480, AH = sb + 40960, AL = sb + 46080;

    int tid = threadIdx.x, wid = tid >> 5, lane = tid & 31;
    int m0 = blockIdx.x * 64;
    int b0 = m0 / S;
    int b1 = (b0 + 1 < B) ? b0 + 1 : b0;
    int bswitch = (b0 + 1) * S - m0;
    int wr = (wid & 1) * 32, wc = (wid >> 1) * 64;
    int lr = lane & 7, sect = lane >> 3;
    uint32_t aoff = (uint32_t)((wr + (sect & 1)*8 + lr)*80 + (sect >> 1)*16);
    uint32_t boff = (uint32_t)((wc + (sect >> 1)*8 + lr)*80 + (sect & 1)*16);

    swsA[tid] = g_wsapp[b0*H + tid];
    swsB[tid] = g_wsapp[b1*H + tid];
    sawc[tid] = awc[tid];
    sav[tid]  = av[tid];
    if (tid < 64) scov[tid] = coverage[(size_t)m0 + tid];

    float acc[2][8][4];
    #pragma unroll
    for (int i = 0; i < 2; i++)
        #pragma unroll
        for (int j = 0; j < 8; j++)
            #pragma unroll
            for (int e = 0; e < 4; e++) acc[i][j][e] = 0.f;

    for (int kc = 0; kc < E; kc += 32) {
        {   // A (fp32 enc_out): row = tid>>2, 8 floats at (tid&3)*8
            int r = tid >> 2, kb = (tid & 3) * 8;
            const float4* src = (const float4*)(A + (size_t)(m0 + r)*E + kc + kb);
            st_hilo(AHc, ALc, r, kb,     src[0]);
            st_hilo(AHc, ALc, r, kb + 4, src[1]);
        }
        {   // W (bf16 pre-split): row = tid, 32 halves hi + lo
            const uint4* sH = (const uint4*)(Wh + (size_t)tid*E + kc);
            const uint4* sL = (const uint4*)(Wl + (size_t)tid*E + kc);
            int off = tid*80;
            #pragma unroll
            for (int i = 0; i < 4; i++) {
                *(uint4*)(WHc + off + i*16) = sH[i];
                *(uint4*)(WLc + off + i*16) = sL[i];
            }
        }
        __syncthreads();
        #pragma unroll
        for (int ks = 0; ks < 64; ks += 32)
            mma_step(acc, AH + aoff + ks, AL + aoff + ks, WH + boff + ks, WL + boff + ks);
        __syncthreads();
    }

    int gid = lane >> 2, t4 = lane & 3;
    #pragma unroll
    for (int mt = 0; mt < 2; mt++)
        #pragma unroll
        for (int eh = 0; eh < 2; eh++) {
            int row = wr + mt*16 + eh*8 + gid;
            float c = scov[row];
            const float* sws = (row < bswitch) ? swsA : swsB;
            float p = 0.f;
            #pragma unroll
            for (int nt = 0; nt < 8; nt++)
                #pragma unroll
                for (int e2 = 0; e2 < 2; e2++) {
                    int h = wc + nt*8 + 2*t4 + e2;
                    float x = acc[mt][nt][eh*2 + e2] + sws[h] + c * sawc[h];
                    p += tanhf(x) * sav[h];
                }
            p += __shfl_xor_sync(0xffffffffu, p, 1);
            p += __shfl_xor_sync(0xffffffffu, p, 2);
            if (t4 == 0) sred[row*4 + (wid >> 1)] = p;
        }
    __syncthreads();
    if (tid < 64)
        g_energy[(size_t)m0 + tid] = sred[tid*4] + sred[tid*4+1] + sred[tid*4+2] + sred[tid*4+3];
}

// ---------- LSTM + p_gen (+ h_t bf16 split) ----------
__global__ void k_lstm(const float* __restrict__ c0, const float* __restrict__ ws,
                       float* __restrict__ out) {
    int b = blockIdx.x, h = threadIdx.x;
    __shared__ float red[32];
    const float* g = g_gates + (size_t)b*G4;
    float ig = sigmoidf_(g[h]);
    float fg = sigmoidf_(g[H + h]);
    float gg = tanhf(g[2*H + h]);
    float og = sigmoidf_(g[3*H + h]);
    float c  = fg * c0[b*H + h] + ig * gg;
    float ht = og * tanhf(c);
    out[OUT_CT + (size_t)b*H + h] = c;
    out[OUT_HT + (size_t)b*H + h] = ht;
    split2(ht, &g_htH[b*H + h], &g_htL[b*H + h]);
    float hw = blk_sum(ht * ws[h], red);
    if (h == 0) g_pgen[b] = sigmoidf_(g_cwp[b] + g_cwp[B + b] + hw + g_exw[b]);
}

// ---------- vocab softmax ----------
__global__ void k_rowstats(const float* __restrict__ out) {
    int b = blockIdx.x, tid = threadIdx.x;
    const float* row = out + (size_t)b*V;
    float m = -1e30f, s = 0.f;
    for (int v = tid; v < V; v += 1024) {
        float x = row[v];
        if (x > m) { s = s*expf(m - x) + 1.f; m = x; }
        else       { s += expf(x - m); }
    }
    __shared__ float sm_[1024], ss[1024];
    sm_[tid] = m; ss[tid] = s;
    __syncthreads();
    for (int off = 512; off; off >>= 1) {
        if (tid < off) {
            float m2 = sm_[tid+off], s2 = ss[tid+off];
            float M = fmaxf(sm_[tid], m2);
            ss[tid] = ss[tid]*expf(sm_[tid] - M) + s2*expf(m2 - M);
            sm_[tid] = M;
        }
        __syncthreads();
    }
    if (tid == 0) { g_rowmax[b] = sm_[0]; g_rowinv[b] = 1.f/ss[0]; }
}
__global__ void k_norm(float* __restrict__ out) {
    size_t idx = (size_t)blockIdx.x*blockDim.x + threadIdx.x;
    if (idx < (size_t)B*V) {
        int b = (int)(idx / V);
        out[idx] = g_pgen[b] * expf(out[idx] - g_rowmax[b]) * g_rowinv[b];
    }
}

// ---------- attention softmax + coverage + loss ----------
__global__ void k_attn(const float* __restrict__ coverage, float* __restrict__ out) {
    int b = blockIdx.x, tid = threadIdx.x;
    __shared__ float red[32];
    float e = (tid < S) ? g_energy[b*S + tid] : -1e30f;
    float m = blk_max(e, red);
    float ex = (tid < S) ? expf(e - m) : 0.f;
    float sum = blk_sum(ex, red);
    float part = 0.f;
    if (tid < S) {
        float a = ex / sum;
        out[OUT_ATTN + (size_t)b*S + tid] = a;
        float c = coverage[(size_t)b*S + tid];
        out[OUT_COV + (size_t)b*S + tid] = c + a;
        part = fminf(a, c);
    }
    float ps = blk_sum(part, red);
    if (tid == 0) g_covpart[b] = ps;
}
__global__ void k_loss(float* __restrict__ out) {
    __shared__ float red[32];
    float s = blk_sum(g_covpart[threadIdx.x], red);
    if (threadIdx.x == 0) out[OUT_LOSS] = s;
}

// ---------- scatter (last-s-wins) ----------
__global__ void k_scatter(const int* __restrict__ enc_inputs, float* __restrict__ out) {
    int b = blockIdx.x, tid = threadIdx.x;
    __shared__ int   sidx[S];
    __shared__ float sat[S];
    if (tid < S) {
        sidx[tid] = enc_inputs[(size_t)b*S + tid];
        sat[tid]  = out[OUT_ATTN + (size_t)b*S + tid];
    }
    __syncthreads();
    if (tid < S) {
        int v = sidx[tid];
        bool win = true;
        for (int s2 = tid + 1; s2 < S; s2++)
            if (sidx[s2] == v) { win = false; break; }
        if (win) out[(size_t)b*V + v] += (1.f - g_pgen[b]) * sat[tid];
    }
}

// ---------- host ----------
extern "C" void kernel_launch(void* const* d_in, const int* in_sizes, int n_in,
                              void* d_out, int out_size) {
    const float* coverage   = (const float*)d_in[0];
    const float* enc_out    = (const float*)d_in[1];
    const float* h0         = (const float*)d_in[2];
    const float* c0         = (const float*)d_in[3];
    const float* attn       = (const float*)d_in[4];
    const int*   dec_input  = (const int*)d_in[5];
    const int*   enc_inputs = (const int*)d_in[6];
    const float* emb_table  = (const float*)d_in[7];
    const float* W_ih       = (const float*)d_in[8];
    const float* W_hh       = (const float*)d_in[9];
    const float* b_ih       = (const float*)d_in[10];
    const float* b_hh       = (const float*)d_in[11];
    const float* awh_W      = (const float*)d_in[12];
    const float* awh_b      = (const float*)d_in[13];
    const float* aws_W      = (const float*)d_in[14];
    const float* aws_b      = (const float*)d_in[15];
    const float* awc        = (const float*)d_in[16];
    const float* av         = (const float*)d_in[17];
    const float* wh         = (const float*)d_in[18];
    const float* ws         = (const float*)d_in[19];
    const float* wx         = (const float*)d_in[20];
    const float* v_W        = (const float*)d_in[21];
    const float* v_b        = (const float*)d_in[22];
    float* out = (float*)d_out;

    float *p_bcat, *p_gates, *p_wsapp, *p_bias2;
    __nv_bfloat16 *p_WcatH, *p_WcatL, *p_xcatH, *p_xcatL, *p_awhH, *p_awhL;
    __nv_bfloat16 *p_awsH, *p_awsL, *p_vWH, *p_vWL, *p_htH, *p_htL;
    cudaGetSymbolAddress((void**)&p_bcat,  g_bcat);
    cudaGetSymbolAddress((void**)&p_gates, g_gates);
    cudaGetSymbolAddress((void**)&p_wsapp, g_wsapp);
    cudaGetSymbolAddress((void**)&p_bias2, g_bias2);
    cudaGetSymbolAddress((void**)&p_WcatH, g_WcatH);
    cudaGetSymbolAddress((void**)&p_WcatL, g_WcatL);
    cudaGetSymbolAddress((void**)&p_xcatH, g_xcatH);
    cudaGetSymbolAddress((void**)&p_xcatL, g_xcatL);
    cudaGetSymbolAddress((void**)&p_awhH,  g_awhH);
    cudaGetSymbolAddress((void**)&p_awhL,  g_awhL);
    cudaGetSymbolAddress((void**)&p_awsH,  g_awsH);
    cudaGetSymbolAddress((void**)&p_awsL,  g_awsL);
    cudaGetSymbolAddress((void**)&p_vWH,   g_vWH);
    cudaGetSymbolAddress((void**)&p_vWL,   g_vWL);
    cudaGetSymbolAddress((void**)&p_htH,   g_htH);
    cudaGetSymbolAddress((void**)&p_htL,   g_htL);

    cudaFuncSetAttribute(fk_whenergy, cudaFuncAttributeMaxDynamicSharedMemorySize, FK_SMEM);

    k_context<<<dim3(B, 2), 256>>>(attn, enc_out, dec_input, emb_table, wh, wx);
    k_packw<<<(G4*KX + 255)/256, 256>>>(W_ih, W_hh, b_ih, b_hh);
    k_bias2<<<1, H>>>(aws_b, awh_b);
    k_cvt<<<(H*E/4 + 255)/256, 256>>>(awh_W, p_awhH, p_awhL, H*E);
    k_cvt<<<(H*H/4 + 255)/256, 256>>>(aws_W, p_awsH, p_awsL, H*H);
    k_cvt<<<(V*H/4 + 255)/256, 256>>>(v_W, p_vWH, p_vWL, V*H);
    k_packx<<<(B*KX + 255)/256, 256>>>(h0);
    // gates = xcat @ Wcat^T + bcat
    hgemm<<<dim3(G4/128, B/128), 256>>>(p_xcatH, p_xcatL, p_WcatH, p_WcatL, p_bcat, p_gates, G4, KX);
    k_lstm<<<B, 256>>>(c0, ws, out);
    // ws_app_eff = h_t @ aws_W^T + (aws_b + awh_b)
    hgemm<<<dim3(H/128, B/128), 256>>>(p_htH, p_htL, p_awsH, p_awsL, p_bias2, p_wsapp, H, H);
    // fused wh_app GEMM + energy
    fk_whenergy<<<(B*S)/64, 256, FK_SMEM>>>(enc_out, p_awhH, p_awhL, coverage, awc, av);
    // logits = h_t @ v_W^T + v_b
    hgemm<<<dim3((V + 127)/128, B/128), 256>>>(p_htH, p_htL, p_vWH, p_vWL, v_b, out, V, H);
    k_rowstats<<<B, 1024>>>(out);
    k_norm<<<(int)(((size_t)B*V + 255)/256), 256>>>(out);
    k_attn<<<B, 512>>>(coverage, out);
    k_loss<<<1, B>>>(out);
    k_scatter<<<B, 512>>>(enc_inputs, out);
}

// round 8
// speedup vs baseline: 2.1671x; 1.2133x over previous
#include <cuda_runtime.h>
#include <cuda_bf16.h>
#include <math.h>
#include <stdint.h>

#define B 512
#define S 400
#define V 50000
#define E 512
#define H 256
#define EMB 128
#define KX (E + EMB + H)
#define G4 (4*H)

#define OUT_COV    ((size_t)B*V)
#define OUT_HT     (OUT_COV  + (size_t)B*S)
#define OUT_CT     (OUT_HT   + (size_t)B*H)
#define OUT_ATTN   (OUT_CT   + (size_t)B*H)
#define OUT_LOSS   (OUT_ATTN + (size_t)B*S)

__device__ float g_ctxp[4][B*E];
__device__ float g_embed[B*EMB];
__device__ float g_bcat[G4];
__device__ float g_gates[B*G4];
__device__ float g_cwp[4*B];
__device__ float g_exw[B];
__device__ float g_pgen[B];
__device__ float g_wsapp[B*H];
__device__ float g_bias2[H];
__device__ float g_energy[B*S];
__device__ float g_covpart[B];
__device__ float g_rowmax[B];
__device__ float g_rowinv[B];

__device__ __nv_bfloat16 g_WcatH[G4*KX], g_WcatL[G4*KX];
__device__ __nv_bfloat16 g_xcatH[B*KX],  g_xcatL[B*KX];
__device__ __nv_bfloat16 g_awhH[H*E],    g_awhL[H*E];
__device__ __nv_bfloat16 g_awsH[H*H],    g_awsL[H*H];
__device__ __nv_bfloat16 g_vWH[(size_t)V*H], g_vWL[(size_t)V*H];
__device__ __nv_bfloat16 g_htH[B*H],     g_htL[B*H];

// ---------- helpers ----------
__device__ __forceinline__ uint32_t smem_u32(const void* p) {
    uint32_t a;
    asm("{ .reg .u64 t; cvta.to.shared.u64 t, %1; cvt.u32.u64 %0, t; }" : "=r"(a) : "l"(p));
    return a;
}
__device__ __forceinline__ void ldm_x4(uint32_t* r, uint32_t addr) {
    asm volatile("ldmatrix.sync.aligned.m8n8.x4.shared.b16 {%0,%1,%2,%3}, [%4];"
        : "=r"(r[0]), "=r"(r[1]), "=r"(r[2]), "=r"(r[3]) : "r"(addr));
}
__device__ __forceinline__ void mma16816(float* d, const uint32_t* a, const uint32_t* b) {
    asm volatile("mma.sync.aligned.m16n8k16.row.col.f32.bf16.bf16.f32 "
        "{%0,%1,%2,%3}, {%4,%5,%6,%7}, {%8,%9}, {%0,%1,%2,%3};"
        : "+f"(d[0]), "+f"(d[1]), "+f"(d[2]), "+f"(d[3])
        : "r"(a[0]), "r"(a[1]), "r"(a[2]), "r"(a[3]), "r"(b[0]), "r"(b[1]));
}
__device__ __forceinline__ void cpa(uint32_t dst, const void* src) {
    asm volatile("cp.async.cg.shared.global [%0], [%1], 16;" :: "r"(dst), "l"(src));
}
__device__ __forceinline__ void cpa_z(uint32_t dst, const void* src, int sz) {
    asm volatile("cp.async.cg.shared.global [%0], [%1], 16, %2;" :: "r"(dst), "l"(src), "r"(sz));
}
#define CP_COMMIT() asm volatile("cp.async.commit_group;" ::: "memory")
#define CP_WAIT1()  asm volatile("cp.async.wait_group 1;" ::: "memory")
#define CP_WAIT0()  asm volatile("cp.async.wait_group 0;" ::: "memory")

// fp32 -> bf16 hi/lo into padded smem (row stride 80B)
__device__ __forceinline__ void st_hilo(char* hiB, char* loB, int row, int k, float4 v) {
    int off = row*80 + k*2;
    __nv_bfloat16 h0 = __float2bfloat16(v.x), h1 = __float2bfloat16(v.y),
                  h2 = __float2bfloat16(v.z), h3 = __float2bfloat16(v.w);
    __nv_bfloat16 l0 = __float2bfloat16(v.x - __bfloat162float(h0)),
                  l1 = __float2bfloat16(v.y - __bfloat162float(h1)),
                  l2 = __float2bfloat16(v.z - __bfloat162float(h2)),
                  l3 = __float2bfloat16(v.w - __bfloat162float(h3));
    *(__nv_bfloat162*)(hiB + off)     = __halves2bfloat162(h0, h1);
    *(__nv_bfloat162*)(hiB + off + 4) = __halves2bfloat162(h2, h3);
    *(__nv_bfloat162*)(loB + off)     = __halves2bfloat162(l0, l1);
    *(__nv_bfloat162*)(loB + off + 4) = __halves2bfloat162(l2, l3);
}
__device__ __forceinline__ void split2(float v, __nv_bfloat16* hp, __nv_bfloat16* lp) {
    __nv_bfloat16 h = __float2bfloat16(v);
    *hp = h;
    *lp = __float2bfloat16(v - __bfloat162float(h));
}
// one 32-k step for a 32x64 warp tile: 3-term bf16
__device__ __forceinline__ void mma_step(float acc[2][8][4],
    uint32_t aHa, uint32_t aLa, uint32_t bHa, uint32_t bLa) {
    uint32_t aH[2][4], aL[2][4], bH[4][4], bL[4][4];
    #pragma unroll
    for (int mt = 0; mt < 2; mt++) { ldm_x4(aH[mt], aHa + mt*1280); ldm_x4(aL[mt], aLa + mt*1280); }
    #pragma unroll
    for (int np = 0; np < 4; np++) { ldm_x4(bH[np], bHa + np*1280); ldm_x4(bL[np], bLa + np*1280); }
    #pragma unroll
    for (int mt = 0; mt < 2; mt++)
        #pragma unroll
        for (int np = 0; np < 4; np++) {
            mma16816(acc[mt][2*np],   aH[mt], bH[np]);
            mma16816(acc[mt][2*np+1], aH[mt], bH[np]+2);
            mma16816(acc[mt][2*np],   aH[mt], bL[np]);
            mma16816(acc[mt][2*np+1], aH[mt], bL[np]+2);
            mma16816(acc[mt][2*np],   aL[mt], bH[np]);
            mma16816(acc[mt][2*np+1], aL[mt], bH[np]+2);
        }
}

__device__ __forceinline__ float sigmoidf_(float x) { return 1.f / (1.f + expf(-x)); }

__device__ __forceinline__ float blk_sum(float v, float* red) {
    int tid = threadIdx.x;
    #pragma unroll
    for (int o = 16; o; o >>= 1) v += __shfl_down_sync(0xffffffffu, v, o);
    if ((tid & 31) == 0) red[tid >> 5] = v;
    __syncthreads();
    float r;
    if (tid < 32) {
        int nw = (blockDim.x + 31) >> 5;
        r = (tid < nw) ? red[tid] : 0.f;
        #pragma unroll
        for (int o = 16; o; o >>= 1) r += __shfl_down_sync(0xffffffffu, r, o);
        if (tid == 0) red[0] = r;
    }
    __syncthreads();
    r = red[0];
    __syncthreads();
    return r;
}
__device__ __forceinline__ float blk_max(float v, float* red) {
    int tid = threadIdx.x;
    #pragma unroll
    for (int o = 16; o; o >>= 1) v = fmaxf(v, __shfl_down_sync(0xffffffffu, v, o));
    if ((tid & 31) == 0) red[tid >> 5] = v;
    __syncthreads();
    float r;
    if (tid < 32) {
        int nw = (blockDim.x + 31) >> 5;
        r = (tid < nw) ? red[tid] : -1e30f;
        #pragma unroll
        for (int o = 16; o; o >>= 1) r = fmaxf(r, __shfl_down_sync(0xffffffffu, r, o));
        if (tid == 0) red[0] = r;
    }
    __syncthreads();
    r = red[0];
    __syncthreads();
    return r;
}

// ---------- generic fp32 -> bf16 hi/lo converter ----------
__global__ void k_cvt(const float* __restrict__ src, __nv_bfloat16* __restrict__ hi,
                      __nv_bfloat16* __restrict__ lo, int n) {
    int idx = (blockIdx.x*blockDim.x + threadIdx.x) * 4;
    if (idx < n) {
        float4 v = *(const float4*)(src + idx);
        __nv_bfloat16 h0, h1, h2, h3, l0, l1, l2, l3;
        split2(v.x, &h0, &l0); split2(v.y, &h1, &l1);
        split2(v.z, &h2, &l2); split2(v.w, &h3, &l3);
        *(__nv_bfloat162*)(hi + idx)     = __halves2bfloat162(h0, h1);
        *(__nv_bfloat162*)(hi + idx + 2) = __halves2bfloat162(h2, h3);
        *(__nv_bfloat162*)(lo + idx)     = __halves2bfloat162(l0, l1);
        *(__nv_bfloat162*)(lo + idx + 2) = __halves2bfloat162(l2, l3);
    }
}

// ---------- context (S quarters), embed, p_gen partials ----------
__global__ void k_context(const float* __restrict__ attn, const float* __restrict__ enc_out,
                          const int* __restrict__ dec_input, const float* __restrict__ emb_table,
                          const float* __restrict__ wh, const float* __restrict__ wx) {
    int b = blockIdx.x, q = blockIdx.y, tid = threadIdx.x;
    __shared__ float sa[S/4];
    __shared__ float red[32];
    int s0 = q * (S/4);
    for (int s = tid; s < S/4; s += 256) sa[s] = attn[(size_t)b*S + s0 + s];
    __syncthreads();
    const float* eb = enc_out + ((size_t)b*S + s0)*E;
    float a0 = 0.f, a1 = 0.f;
    #pragma unroll 4
    for (int s = 0; s < S/4; s++) {
        float a = sa[s];
        a0 += a * eb[(size_t)s*E + tid];
        a1 += a * eb[(size_t)s*E + 256 + tid];
    }
    g_ctxp[q][b*E + tid]       = a0;
    g_ctxp[q][b*E + 256 + tid] = a1;
    float cw = blk_sum(a0*wh[tid] + a1*wh[256+tid], red);
    if (tid == 0) g_cwp[q*B + b] = cw;
    if (q == 0) {
        float ew = 0.f;
        if (tid < EMB) {
            float e = emb_table[(size_t)dec_input[b]*EMB + tid];
            g_embed[b*EMB + tid] = e;
            ew = e * wx[tid];
        }
        float exw = blk_sum(ew, red);
        if (tid == 0) g_exw[b] = exw;
    }
}

__global__ void k_packw(const float* __restrict__ W_ih, const float* __restrict__ W_hh,
                        const float* __restrict__ b_ih, const float* __restrict__ b_hh) {
    int idx = blockIdx.x*blockDim.x + threadIdx.x;
    if (idx < G4*KX) {
        int n = idx / KX, k = idx % KX;
        float w = (k < E+EMB) ? W_ih[(size_t)n*(E+EMB) + k] : W_hh[(size_t)n*H + (k - (E+EMB))];
        split2(w, &g_WcatH[idx], &g_WcatL[idx]);
    }
    if (idx < G4) g_bcat[idx] = b_ih[idx] + b_hh[idx];
}
__global__ void k_packx(const float* __restrict__ h0) {
    int idx = blockIdx.x*blockDim.x + threadIdx.x;
    if (idx < B*KX) {
        int b = idx / KX, k = idx % KX;
        float v;
        if (k < E)          v = g_ctxp[0][b*E+k] + g_ctxp[1][b*E+k] + g_ctxp[2][b*E+k] + g_ctxp[3][b*E+k];
        else if (k < E+EMB) v = g_embed[b*EMB + (k - E)];
        else                v = h0[b*H + (k - E - EMB)];
        split2(v, &g_xcatH[idx], &g_xcatL[idx]);
    }
}
__global__ void k_bias2(const float* __restrict__ aws_b, const float* __restrict__ awh_b) {
    g_bias2[threadIdx.x] = aws_b[threadIdx.x] + awh_b[threadIdx.x];
}

// ---------- HMMA GEMM, cp.async double-buffered: tile 128x128, K-chunk 32 ----------
// stage layout: AH 0, AL 10240, WH 20480, WL 30720 (40960 per stage, 2 stages)
#define HG_STAGE 40960
#define HG_SMEM  81920
__global__ void __launch_bounds__(256) hgemm(
        const __nv_bfloat16* __restrict__ Ah, const __nv_bfloat16* __restrict__ Al,
        const __nv_bfloat16* __restrict__ Wh, const __nv_bfloat16* __restrict__ Wl,
        const float* __restrict__ bias, float* __restrict__ C, int N, int K) {
    extern __shared__ __align__(16) char sm[];
    uint32_t sb = smem_u32(sm);

    int tid = threadIdx.x, wid = tid >> 5, lane = tid & 31;
    int m0 = blockIdx.y * 128, n0 = blockIdx.x * 128;
    int wr = (wid & 3) * 32, wc = (wid >> 2) * 64;
    int lr = lane & 7, sect = lane >> 3;
    uint32_t aoff = (uint32_t)((wr + (sect & 1)*8 + lr)*80 + (sect >> 1)*16);
    uint32_t boff = (uint32_t)((wc + (sect >> 1)*8 + lr)*80 + (sect & 1)*16);

    int r = tid >> 1, kb = (tid & 1) * 16;          // kb in halves
    uint32_t doff = (uint32_t)(r*80 + kb*2);
    const char* aHs = (const char*)(Ah + (size_t)(m0 + r)*K + kb);
    const char* aLs = (const char*)(Al + (size_t)(m0 + r)*K + kb);
    int n = n0 + r;
    int wsz = (n < N) ? 16 : 0;
    int nc = (n < N) ? n : 0;
    const char* wHs = (const char*)(Wh + (size_t)nc*K + kb);
    const char* wLs = (const char*)(Wl + (size_t)nc*K + kb);

    float acc[2][8][4];
    #pragma unroll
    for (int i = 0; i < 2; i++)
        #pragma unroll
        for (int j = 0; j < 8; j++)
            #pragma unroll
            for (int e = 0; e < 4; e++) acc[i][j][e] = 0.f;

    const int NC = K / 32;
    // prologue: chunk 0 -> stage 0
    #pragma unroll
    for (int i = 0; i < 2; i++) {
        cpa(sb + doff + i*16,          aHs + i*16);
        cpa(sb + 10240 + doff + i*16,  aLs + i*16);
        cpa_z(sb + 20480 + doff + i*16, wHs + i*16, wsz);
        cpa_z(sb + 30720 + doff + i*16, wLs + i*16, wsz);
    }
    CP_COMMIT();

    for (int c = 0; c < NC; c++) {
        uint32_t st = sb + (uint32_t)((c & 1) * HG_STAGE);
        if (c + 1 < NC) {
            uint32_t st2 = sb + (uint32_t)(((c+1) & 1) * HG_STAGE);
            int ko = (c + 1) * 64;   // bytes
            #pragma unroll
            for (int i = 0; i < 2; i++) {
                cpa(st2 + doff + i*16,          aHs + ko + i*16);
                cpa(st2 + 10240 + doff + i*16,  aLs + ko + i*16);
                cpa_z(st2 + 20480 + doff + i*16, wHs + ko + i*16, wsz);
                cpa_z(st2 + 30720 + doff + i*16, wLs + ko + i*16, wsz);
            }
            CP_COMMIT();
            CP_WAIT1();
        } else CP_WAIT0();
        __syncthreads();
        #pragma unroll
        for (int ks = 0; ks < 64; ks += 32)
            mma_step(acc, st + aoff + ks, st + 10240 + aoff + ks,
                          st + 20480 + boff + ks, st + 30720 + boff + ks);
        __syncthreads();
    }

    int gid = lane >> 2, t4 = lane & 3;
    #pragma unroll
    for (int mt = 0; mt < 2; mt++)
        #pragma unroll
        for (int eh = 0; eh < 2; eh++) {
            size_t row = (size_t)(m0 + wr + mt*16 + eh*8 + gid);
            #pragma unroll
            for (int nt = 0; nt < 8; nt++) {
                int col = n0 + wc + nt*8 + 2*t4;
                if (col + 1 < N) {
                    float2 v;
                    v.x = acc[mt][nt][eh*2+0] + bias[col];
                    v.y = acc[mt][nt][eh*2+1] + bias[col+1];
                    *(float2*)&C[row*(size_t)N + col] = v;
                } else if (col < N) {
                    C[row*(size_t)N + col] = acc[mt][nt][eh*2] + bias[col];
                }
            }
        }
}

// ---------- fused wh_app GEMM + energy, cp.async double-buffered: tile 64x256 ----------
// stage: WH 0, WL 20480, AH 40960, AL 46080 (51200/stage, 2 stages), floats at 102400
#define FK_STAGE 51200
#define FK_FLT   102400
#define FK_SMEM  107776
__global__ void __launch_bounds__(256) fk_whenergy(const float* __restrict__ A,
        const __nv_bfloat16* __restrict__ Wh, const __nv_bfloat16* __restrict__ Wl,
        const float* __restrict__ coverage,
        const float* __restrict__ awc, const float* __restrict__ av) {
    extern __shared__ __align__(16) char sm[];
    uint32_t sb = smem_u32(sm);
    float* swsA = (float*)(sm + FK_FLT);
    float* swsB = (float*)(sm + FK_FLT + 1024);
    float* sawc = (float*)(sm + FK_FLT + 2048);
    float* sav  = (float*)(sm + FK_FLT + 3072);
    float* scov = (float*)(sm + FK_FLT + 4096);
    float* sred = (float*)(sm + FK_FLT + 4352);

    int tid = threadIdx.x, wid = tid >> 5, lane = tid & 31;
    int m0 = blockIdx.x * 64;
    int b0 = m0 / S;
    int b1 = (b0 + 1 < B) ? b0 + 1 : b0;
    int bswitch = (b0 + 1) * S - m0;
    int wr = (wid & 1) * 32, wc = (wid >> 1) * 64;
    int lr = lane & 7, sect = lane >> 3;
    uint32_t aoff = (uint32_t)((wr + (sect & 1)*8 + lr)*80 + (sect >> 1)*16);
    uint32_t boff = (uint32_t)((wc + (sect >> 1)*8 + lr)*80 + (sect & 1)*16);

    swsA[tid] = g_wsapp[b0*H + tid];
    swsB[tid] = g_wsapp[b1*H + tid];
    sawc[tid] = awc[tid];
    sav[tid]  = av[tid];
    if (tid < 64) scov[tid] = coverage[(size_t)m0 + tid];

    // W cp.async: row = tid (256 rows), 64B hi + 64B lo per chunk
    const char* wHs = (const char*)(Wh + (size_t)tid*E);
    const char* wLs = (const char*)(Wl + (size_t)tid*E);
    uint32_t wdoff = (uint32_t)(tid*80);
    // A: row = tid>>2, 8 floats at (tid&3)*8
    int ar = tid >> 2, akb = (tid & 3) * 8;
    const float* aSrc = A + (size_t)(m0 + ar)*E + akb;

    float acc[2][8][4];
    #pragma unroll
    for (int i = 0; i < 2; i++)
        #pragma unroll
        for (int j = 0; j < 8; j++)
            #pragma unroll
            for (int e = 0; e < 4; e++) acc[i][j][e] = 0.f;

    // prologue: W[0] -> stage 0, A[0] -> regs
    #pragma unroll
    for (int i = 0; i < 4; i++) {
        cpa(sb + wdoff + i*16,         wHs + i*16);
        cpa(sb + 20480 + wdoff + i*16, wLs + i*16);
    }
    CP_COMMIT();
    float4 aN0 = *(const float4*)(aSrc);
    float4 aN1 = *(const float4*)(aSrc + 4);

    for (int c = 0; c < E/32; c++) {
        uint32_t st = sb + (uint32_t)((c & 1) * FK_STAGE);
        char* stc = sm + (c & 1) * FK_STAGE;
        // convert+store A[c] into this stage
        st_hilo(stc + 40960, stc + 46080, ar, akb,     aN0);
        st_hilo(stc + 40960, stc + 46080, ar, akb + 4, aN1);
        if (c + 1 < E/32) {
            uint32_t st2 = sb + (uint32_t)(((c+1) & 1) * FK_STAGE);
            int ko = (c + 1) * 64;  // bytes
            #pragma unroll
            for (int i = 0; i < 4; i++) {
                cpa(st2 + wdoff + i*16,         wHs + ko + i*16);
                cpa(st2 + 20480 + wdoff + i*16, wLs + ko + i*16);
            }
            CP_COMMIT();
            aN0 = *(const float4*)(aSrc + (c+1)*32);
            aN1 = *(const float4*)(aSrc + (c+1)*32 + 4);
            CP_WAIT1();
        } else CP_WAIT0();
        __syncthreads();
        #pragma unroll
        for (int ks = 0; ks < 64; ks += 32)
            mma_step(acc, st + 40960 + aoff + ks, st + 46080 + aoff + ks,
                          st + boff + ks,         st + 20480 + boff + ks);
        __syncthreads();
    }

    int gid = lane >> 2, t4 = lane & 3;
    #pragma unroll
    for (int mt = 0; mt < 2; mt++)
        #pragma unroll
        for (int eh = 0; eh < 2; eh++) {
            int row = wr + mt*16 + eh*8 + gid;
            float c = scov[row];
            const float* sws = (row < bswitch) ? swsA : swsB;
            float p = 0.f;
            #pragma unroll
            for (int nt = 0; nt < 8; nt++)
                #pragma unroll
                for (int e2 = 0; e2 < 2; e2++) {
                    int h = wc + nt*8 + 2*t4 + e2;
                    float x = acc[mt][nt][eh*2 + e2] + sws[h] + c * sawc[h];
                    p += tanhf(x) * sav[h];
                }
            p += __shfl_xor_sync(0xffffffffu, p, 1);
            p += __shfl_xor_sync(0xffffffffu, p, 2);
            if (t4 == 0) sred[row*4 + (wid >> 1)] = p;
        }
    __syncthreads();
    if (tid < 64)
        g_energy[(size_t)m0 + tid] = sred[tid*4] + sred[tid*4+1] + sred[tid*4+2] + sred[tid*4+3];
}

// ---------- LSTM + p_gen ----------
__global__ void k_lstm(const float* __restrict__ c0, const float* __restrict__ ws,
                       float* __restrict__ out) {
    int b = blockIdx.x, h = threadIdx.x;
    __shared__ float red[32];
    const float* g = g_gates + (size_t)b*G4;
    float ig = sigmoidf_(g[h]);
    float fg = sigmoidf_(g[H + h]);
    float gg = tanhf(g[2*H + h]);
    float og = sigmoidf_(g[3*H + h]);
    float c  = fg * c0[b*H + h] + ig * gg;
    float ht = og * tanhf(c);
    out[OUT_CT + (size_t)b*H + h] = c;
    out[OUT_HT + (size_t)b*H + h] = ht;
    split2(ht, &g_htH[b*H + h], &g_htL[b*H + h]);
    float hw = blk_sum(ht * ws[h], red);
    if (h == 0)
        g_pgen[b] = sigmoidf_(g_cwp[b] + g_cwp[B+b] + g_cwp[2*B+b] + g_cwp[3*B+b] + hw + g_exw[b]);
}

// ---------- vocab softmax ----------
__global__ void k_rowstats(const float* __restrict__ out) {
    int b = blockIdx.x, tid = threadIdx.x;
    const float* row = out + (size_t)b*V;
    float m = -1e30f, s = 0.f;
    for (int v = tid; v < V; v += 1024) {
        float x = row[v];
        if (x > m) { s = s*expf(m - x) + 1.f; m = x; }
        else       { s += expf(x - m); }
    }
    __shared__ float sm_[1024], ss[1024];
    sm_[tid] = m; ss[tid] = s;
    __syncthreads();
    for (int off = 512; off; off >>= 1) {
        if (tid < off) {
            float m2 = sm_[tid+off], s2 = ss[tid+off];
            float M = fmaxf(sm_[tid], m2);
            ss[tid] = ss[tid]*expf(sm_[tid] - M) + s2*expf(m2 - M);
            sm_[tid] = M;
        }
        __syncthreads();
    }
    if (tid == 0) { g_rowmax[b] = sm_[0]; g_rowinv[b] = 1.f/ss[0]; }
}
__global__ void k_norm(float* __restrict__ out) {
    size_t idx = (size_t)blockIdx.x*blockDim.x + threadIdx.x;
    if (idx < (size_t)B*V) {
        int b = (int)(idx / V);
        out[idx] = g_pgen[b] * expf(out[idx] - g_rowmax[b]) * g_rowinv[b];
    }
}

// ---------- attention softmax + coverage + loss ----------
__global__ void k_attn(const float* __restrict__ coverage, float* __restrict__ out) {
    int b = blockIdx.x, tid = threadIdx.x;
    __shared__ float red[32];
    float e = (tid < S) ? g_energy[b*S + tid] : -1e30f;
    float m = blk_max(e, red);
    float ex = (tid < S) ? expf(e - m) : 0.f;
    float sum = blk_sum(ex, red);
    float part = 0.f;
    if (tid < S) {
        float a = ex / sum;
        out[OUT_ATTN + (size_t)b*S + tid] = a;
        float c = coverage[(size_t)b*S + tid];
        out[OUT_COV + (size_t)b*S + tid] = c + a;
        part = fminf(a, c);
    }
    float ps = blk_sum(part, red);
    if (tid == 0) g_covpart[b] = ps;
}
__global__ void k_loss(float* __restrict__ out) {
    __shared__ float red[32];
    float s = blk_sum(g_covpart[threadIdx.x], red);
    if (threadIdx.x == 0) out[OUT_LOSS] = s;
}

// ---------- scatter (last-s-wins) ----------
__global__ void k_scatter(const int* __restrict__ enc_inputs, float* __restrict__ out) {
    int b = blockIdx.x, tid = threadIdx.x;
    __shared__ int   sidx[S];
    __shared__ float sat[S];
    if (tid < S) {
        sidx[tid] = enc_inputs[(size_t)b*S + tid];
        sat[tid]  = out[OUT_ATTN + (size_t)b*S + tid];
    }
    __syncthreads();
    if (tid < S) {
        int v = sidx[tid];
        bool win = true;
        for (int s2 = tid + 1; s2 < S; s2++)
            if (sidx[s2] == v) { win = false; break; }
        if (win) out[(size_t)b*V + v] += (1.f - g_pgen[b]) * sat[tid];
    }
}

// ---------- host ----------
extern "C" void kernel_launch(void* const* d_in, const int* in_sizes, int n_in,
                              void* d_out, int out_size) {
    const float* coverage   = (const float*)d_in[0];
    const float* enc_out    = (const float*)d_in[1];
    const float* h0         = (const float*)d_in[2];
    const float* c0         = (const float*)d_in[3];
    const float* attn       = (const float*)d_in[4];
    const int*   dec_input  = (const int*)d_in[5];
    const int*   enc_inputs = (const int*)d_in[6];
    const float* emb_table  = (const float*)d_in[7];
    const float* W_ih       = (const float*)d_in[8];
    const float* W_hh       = (const float*)d_in[9];
    const float* b_ih       = (const float*)d_in[10];
    const float* b_hh       = (const float*)d_in[11];
    const float* awh_W      = (const float*)d_in[12];
    const float* awh_b      = (const float*)d_in[13];
    const float* aws_W      = (const float*)d_in[14];
    const float* aws_b      = (const float*)d_in[15];
    const float* awc        = (const float*)d_in[16];
    const float* av         = (const float*)d_in[17];
    const float* wh         = (const float*)d_in[18];
    const float* ws         = (const float*)d_in[19];
    const float* wx         = (const float*)d_in[20];
    const float* v_W        = (const float*)d_in[21];
    const float* v_b        = (const float*)d_in[22];
    float* out = (float*)d_out;

    float *p_bcat, *p_gates, *p_wsapp, *p_bias2;
    __nv_bfloat16 *p_WcatH, *p_WcatL, *p_xcatH, *p_xcatL, *p_awhH, *p_awhL;
    __nv_bfloat16 *p_awsH, *p_awsL, *p_vWH, *p_vWL, *p_htH, *p_htL;
    cudaGetSymbolAddress((void**)&p_bcat,  g_bcat);
    cudaGetSymbolAddress((void**)&p_gates, g_gates);
    cudaGetSymbolAddress((void**)&p_wsapp, g_wsapp);
    cudaGetSymbolAddress((void**)&p_bias2, g_bias2);
    cudaGetSymbolAddress((void**)&p_WcatH, g_WcatH);
    cudaGetSymbolAddress((void**)&p_WcatL, g_WcatL);
    cudaGetSymbolAddress((void**)&p_xcatH, g_xcatH);
    cudaGetSymbolAddress((void**)&p_xcatL, g_xcatL);
    cudaGetSymbolAddress((void**)&p_awhH,  g_awhH);
    cudaGetSymbolAddress((void**)&p_awhL,  g_awhL);
    cudaGetSymbolAddress((void**)&p_awsH,  g_awsH);
    cudaGetSymbolAddress((void**)&p_awsL,  g_awsL);
    cudaGetSymbolAddress((void**)&p_vWH,   g_vWH);
    cudaGetSymbolAddress((void**)&p_vWL,   g_vWL);
    cudaGetSymbolAddress((void**)&p_htH,   g_htH);
    cudaGetSymbolAddress((void**)&p_htL,   g_htL);

    cudaFuncSetAttribute(fk_whenergy, cudaFuncAttributeMaxDynamicSharedMemorySize, FK_SMEM);
    cudaFuncSetAttribute(hgemm,       cudaFuncAttributeMaxDynamicSharedMemorySize, HG_SMEM);

    k_context<<<dim3(B, 4), 256>>>(attn, enc_out, dec_input, emb_table, wh, wx);
    k_packw<<<(G4*KX + 255)/256, 256>>>(W_ih, W_hh, b_ih, b_hh);
    k_bias2<<<1, H>>>(aws_b, awh_b);
    k_cvt<<<(H*E/4 + 255)/256, 256>>>(awh_W, p_awhH, p_awhL, H*E);
    k_cvt<<<(H*H/4 + 255)/256, 256>>>(aws_W, p_awsH, p_awsL, H*H);
    k_cvt<<<(V*H/4 + 255)/256, 256>>>(v_W, p_vWH, p_vWL, V*H);
    k_packx<<<(B*KX + 255)/256, 256>>>(h0);
    // gates = xcat @ Wcat^T + bcat
    hgemm<<<dim3(G4/128, B/128), 256, HG_SMEM>>>(p_xcatH, p_xcatL, p_WcatH, p_WcatL, p_bcat, p_gates, G4, KX);
    k_lstm<<<B, 256>>>(c0, ws, out);
    // ws_app_eff = h_t @ aws_W^T + (aws_b + awh_b)
    hgemm<<<dim3(H/128, B/128), 256, HG_SMEM>>>(p_htH, p_htL, p_awsH, p_awsL, p_bias2, p_wsapp, H, H);
    // fused wh_app GEMM + energy
    fk_whenergy<<<(B*S)/64, 256, FK_SMEM>>>(enc_out, p_awhH, p_awhL, coverage, awc, av);
    // logits = h_t @ v_W^T + v_b
    hgemm<<<dim3((V + 127)/128, B/128), 256, HG_SMEM>>>(p_htH, p_htL, p_vWH, p_vWL, v_b, out, V, H);
    k_rowstats<<<B, 1024>>>(out);
    k_norm<<<(int)(((size_t)B*V + 255)/256), 256>>>(out);
    k_attn<<<B, 512>>>(coverage, out);
    k_loss<<<1, B>>>(out);
    k_scatter<<<B, 512>>>(enc_inputs, out);
}